// round 1
// baseline (speedup 1.0000x reference)
#include <cuda_runtime.h>
#include <math.h>

#define L 2048
#define HID 3072
#define HEADS 24
#define HD 128
#define MLPD 12288
#define H1 21504    // 3*HID + MLP
#define CATD 15360  // HID + MLP

// ---------------- scratch (device globals; no allocation allowed) ----------------
__device__ float g_sv[HID];                       // silu(vec)
__device__ float g_m[3 * HID];                    // shift|scale|gate
__device__ float g_xmod[(size_t)L * HID];
__device__ float g_h[(size_t)L * H1];
__device__ float g_y1[3 * (size_t)L * 32];        // lora-down outputs q,k,v
__device__ float g_q[(size_t)HEADS * L * HD];     // [h][l][d]
__device__ float g_k[(size_t)HEADS * L * HD];     // [h][l][d]
__device__ float g_v[(size_t)HEADS * HD * L];     // [h][d][l]  (transposed)
__device__ float g_S[(size_t)HEADS * L * L];      // scores / probs
__device__ float g_cat[(size_t)L * CATD];         // [attn | gelu(mlp)]
__device__ float g_o[(size_t)L * HID];            // cat @ w2^T + b2
__device__ float g_pl[(size_t)L * 64];            // cat @ proj_down^T

// ---------------- silu(vec) ----------------
__global__ void silu_k(const float* __restrict__ vec) {
    int i = blockIdx.x * 256 + threadIdx.x;
    if (i < HID) {
        float v = vec[i];
        g_sv[i] = v / (1.f + expf(-v));
    }
}

// ---------------- m = silu(vec) @ mod_w^T + mod_b  (9216 outputs) ----------------
__global__ __launch_bounds__(256) void mod_gemv(const float* __restrict__ W,
                                                const float* __restrict__ b) {
    int o = blockIdx.x * 8 + (threadIdx.x >> 5);
    int lane = threadIdx.x & 31;
    const float* w = W + (size_t)o * HID;
    float acc = 0.f;
    for (int k = lane; k < HID; k += 32) acc += g_sv[k] * w[k];
    #pragma unroll
    for (int s = 16; s; s >>= 1) acc += __shfl_xor_sync(0xffffffffu, acc, s);
    if (lane == 0) g_m[o] = acc + b[o];
}

// ---------------- x_mod = (1+scale)*LN(x) + shift ----------------
__global__ __launch_bounds__(256) void ln_mod_k(const float* __restrict__ x) {
    int l = blockIdx.x, t = threadIdx.x;
    const float* xr = x + (size_t)l * HID;
    float s = 0.f, s2 = 0.f;
    for (int j = t; j < HID; j += 256) { float v = xr[j]; s += v; s2 += v * v; }
    __shared__ float sh[16];
    #pragma unroll
    for (int o = 16; o; o >>= 1) {
        s  += __shfl_xor_sync(0xffffffffu, s, o);
        s2 += __shfl_xor_sync(0xffffffffu, s2, o);
    }
    if ((t & 31) == 0) { sh[t >> 5] = s; sh[8 + (t >> 5)] = s2; }
    __syncthreads();
    float ts = 0.f, ts2 = 0.f;
    #pragma unroll
    for (int i = 0; i < 8; i++) { ts += sh[i]; ts2 += sh[8 + i]; }
    float mu = ts * (1.f / HID);
    float var = ts2 * (1.f / HID) - mu * mu;
    float r = rsqrtf(var + 1e-6f);
    for (int j = t; j < HID; j += 256) {
        float v = (xr[j] - mu) * r;
        g_xmod[(size_t)l * HID + j] = (1.f + g_m[HID + j]) * v + g_m[j];
    }
}

// ---------------- generic batched NT GEMM: C = scale * A@B^T (+bias) ----------------
// A: (M,K) row-major lda; B: (N,K) row-major ldb; C: (M,N) row-major ldc.
// M = gridDim.y*128, N = gridDim.x*128 (exact), K % 8 == 0.
__global__ __launch_bounds__(256) void gemm_nt(
    const float* __restrict__ A, const float* __restrict__ Bw, float* __restrict__ C,
    const float* __restrict__ bias, int K, int lda, int ldb, int ldc,
    long long sA, long long sB, long long sC, float scale)
{
    int z = blockIdx.z;
    A  += z * sA;  Bw += z * sB;  C += z * sC;

    __shared__ float As[8][128];
    __shared__ float Bs[8][128];

    int t = threadIdx.x;
    int tx = t & 15, ty = t >> 4;            // tx->n, ty->m
    int m0 = blockIdx.y * 128, n0 = blockIdx.x * 128;
    int lrow = t >> 1;
    int lk4  = (t & 1) * 4;

    const float* Ap = A  + (size_t)(m0 + lrow) * lda + lk4;
    const float* Bp = Bw + (size_t)(n0 + lrow) * ldb + lk4;

    float acc[8][8] = {};

    for (int k0 = 0; k0 < K; k0 += 8) {
        float4 av = *(const float4*)(Ap + k0);
        float4 bv = *(const float4*)(Bp + k0);
        As[lk4][lrow] = av.x; As[lk4 + 1][lrow] = av.y;
        As[lk4 + 2][lrow] = av.z; As[lk4 + 3][lrow] = av.w;
        Bs[lk4][lrow] = bv.x; Bs[lk4 + 1][lrow] = bv.y;
        Bs[lk4 + 2][lrow] = bv.z; Bs[lk4 + 3][lrow] = bv.w;
        __syncthreads();
        #pragma unroll
        for (int kk = 0; kk < 8; kk++) {
            float4 a0 = *(const float4*)&As[kk][ty * 8];
            float4 a1 = *(const float4*)&As[kk][ty * 8 + 4];
            float4 b0 = *(const float4*)&Bs[kk][tx * 8];
            float4 b1 = *(const float4*)&Bs[kk][tx * 8 + 4];
            float a[8] = {a0.x, a0.y, a0.z, a0.w, a1.x, a1.y, a1.z, a1.w};
            float b[8] = {b0.x, b0.y, b0.z, b0.w, b1.x, b1.y, b1.z, b1.w};
            #pragma unroll
            for (int i = 0; i < 8; i++)
                #pragma unroll
                for (int j = 0; j < 8; j++) acc[i][j] += a[i] * b[j];
        }
        __syncthreads();
    }

    #pragma unroll
    for (int i = 0; i < 8; i++) {
        int mrow = m0 + ty * 8 + i;
        float v[8];
        #pragma unroll
        for (int j = 0; j < 8; j++) {
            float w = acc[i][j] * scale;
            if (bias) w += bias[n0 + tx * 8 + j];
            v[j] = w;
        }
        float* cp = C + (size_t)mrow * ldc + n0 + tx * 8;
        *(float4*)cp       = make_float4(v[0], v[1], v[2], v[3]);
        *(float4*)(cp + 4) = make_float4(v[4], v[5], v[6], v[7]);
    }
}

// ---------------- lora down: Y(64-row tile, 32 cols) = X @ D^T ----------------
// D: (32, K) row-major; X: (M, K) row-major ldx; Y: ldy. K % 64 == 0.
__global__ __launch_bounds__(256) void lora_down(
    const float* __restrict__ X, int ldx, const float* __restrict__ D,
    float* __restrict__ Y, int ldy, int K)
{
    __shared__ float xs[64][64];
    __shared__ float ds[64][32];
    int t = threadIdx.x;
    int m0 = blockIdx.x * 64;
    int tx = t & 31, ty = t >> 5;
    int xrow = t >> 2, xf4 = t & 3;
    int drow = t >> 3, df4 = t & 7;
    float acc[8] = {};

    for (int k0 = 0; k0 < K; k0 += 64) {
        #pragma unroll
        for (int j = 0; j < 4; j++) {
            int kk = (xf4 + 4 * j) * 4;
            float4 vx = *(const float4*)(X + (size_t)(m0 + xrow) * ldx + k0 + kk);
            xs[kk][xrow] = vx.x; xs[kk + 1][xrow] = vx.y;
            xs[kk + 2][xrow] = vx.z; xs[kk + 3][xrow] = vx.w;
        }
        #pragma unroll
        for (int j = 0; j < 2; j++) {
            int kk = (df4 + 8 * j) * 4;
            float4 vd = *(const float4*)(D + (size_t)drow * K + k0 + kk);
            ds[kk][drow] = vd.x; ds[kk + 1][drow] = vd.y;
            ds[kk + 2][drow] = vd.z; ds[kk + 3][drow] = vd.w;
        }
        __syncthreads();
        #pragma unroll
        for (int kk = 0; kk < 64; kk++) {
            float dv = ds[kk][tx];
            #pragma unroll
            for (int i = 0; i < 8; i++) acc[i] += xs[kk][ty * 8 + i] * dv;
        }
        __syncthreads();
    }
    #pragma unroll
    for (int i = 0; i < 8; i++)
        Y[(size_t)(m0 + ty * 8 + i) * ldy + tx] = acc[i];
}

// ---------------- qkv assembly: lora-up add, RMS norm, RoPE, layout ----------------
__global__ __launch_bounds__(128) void qkv_finalize(
    const float* __restrict__ upq, const float* __restrict__ upk,
    const float* __restrict__ upv, const float* __restrict__ q_scale,
    const float* __restrict__ k_scale, const float* __restrict__ pe)
{
    int head = blockIdx.x, l = blockIdx.y, d = threadIdx.x;
    int col = head * HD + d;

    __shared__ float yq[32], yk[32], yv[32];
    __shared__ float sq[128], sk[128];
    __shared__ float wq[4], wk[4];

    if (d < 32)       yq[d]      = g_y1[(size_t)l * 32 + d];
    else if (d < 64)  yk[d - 32] = g_y1[(size_t)(L + l) * 32 + (d - 32)];
    else if (d < 96)  yv[d - 64] = g_y1[(size_t)(2 * L + l) * 32 + (d - 64)];
    __syncthreads();

    size_t hb = (size_t)l * H1;
    float qv = g_h[hb + col];
    float kv = g_h[hb + HID + col];
    float vv = g_h[hb + 2 * HID + col];

    {
        const float4* u = (const float4*)(upq + (size_t)col * 32);
        float a = 0.f;
        #pragma unroll
        for (int r = 0; r < 8; r++) {
            float4 t4 = u[r];
            a += t4.x * yq[4 * r] + t4.y * yq[4 * r + 1] + t4.z * yq[4 * r + 2] + t4.w * yq[4 * r + 3];
        }
        qv += a;
    }
    {
        const float4* u = (const float4*)(upk + (size_t)col * 32);
        float a = 0.f;
        #pragma unroll
        for (int r = 0; r < 8; r++) {
            float4 t4 = u[r];
            a += t4.x * yk[4 * r] + t4.y * yk[4 * r + 1] + t4.z * yk[4 * r + 2] + t4.w * yk[4 * r + 3];
        }
        kv += a;
    }
    {
        const float4* u = (const float4*)(upv + (size_t)col * 32);
        float a = 0.f;
        #pragma unroll
        for (int r = 0; r < 8; r++) {
            float4 t4 = u[r];
            a += t4.x * yv[4 * r] + t4.y * yv[4 * r + 1] + t4.z * yv[4 * r + 2] + t4.w * yv[4 * r + 3];
        }
        vv += a;
    }

    sq[d] = qv; sk[d] = kv;
    float aq = qv * qv, ak = kv * kv;
    #pragma unroll
    for (int o = 16; o; o >>= 1) {
        aq += __shfl_xor_sync(0xffffffffu, aq, o);
        ak += __shfl_xor_sync(0xffffffffu, ak, o);
    }
    if ((d & 31) == 0) { wq[d >> 5] = aq; wk[d >> 5] = ak; }
    __syncthreads();

    float rq = rsqrtf((wq[0] + wq[1] + wq[2] + wq[3]) * (1.f / HD) + 1e-6f);
    float rk = rsqrtf((wk[0] + wk[1] + wk[2] + wk[3]) * (1.f / HD) + 1e-6f);

    int e = d & ~1, o_ = d | 1;
    float q0 = sq[e]  * rq * q_scale[e];
    float q1 = sq[o_] * rq * q_scale[o_];
    float k0 = sk[e]  * rk * k_scale[e];
    float k1 = sk[o_] * rk * k_scale[o_];

    // pe[l][i][a][b] at l*256 + i*4 + a*2 + b;  [0][0]=cos [0][1]=-sin [1][0]=sin [1][1]=cos
    const float* p = pe + ((size_t)l * 64 + (d >> 1)) * 4;
    float qo = (d & 1) ? (p[2] * q0 + p[3] * q1) : (p[0] * q0 + p[1] * q1);
    float ko = (d & 1) ? (p[2] * k0 + p[3] * k1) : (p[0] * k0 + p[1] * k1);

    size_t base = ((size_t)head * L + l) * HD + d;
    g_q[base] = qo;
    g_k[base] = ko;
    g_v[((size_t)head * HD + d) * L + l] = vv;   // transposed for PV NT-GEMM
}

// ---------------- softmax over 2048-wide rows ----------------
__global__ __launch_bounds__(256) void softmax_k() {
    float* p = g_S + (size_t)blockIdx.x * L;
    int t = threadIdx.x;
    __shared__ float sh[8];

    float mx = -1e30f;
    for (int j = t; j < L; j += 256) mx = fmaxf(mx, p[j]);
    #pragma unroll
    for (int o = 16; o; o >>= 1) mx = fmaxf(mx, __shfl_xor_sync(0xffffffffu, mx, o));
    if ((t & 31) == 0) sh[t >> 5] = mx;
    __syncthreads();
    float m2 = sh[0];
    #pragma unroll
    for (int i = 1; i < 8; i++) m2 = fmaxf(m2, sh[i]);
    __syncthreads();

    float sum = 0.f;
    for (int j = t; j < L; j += 256) {
        float e = __expf(p[j] - m2);
        p[j] = e;
        sum += e;
    }
    #pragma unroll
    for (int o = 16; o; o >>= 1) sum += __shfl_xor_sync(0xffffffffu, sum, o);
    if ((t & 31) == 0) sh[t >> 5] = sum;
    __syncthreads();
    float s2 = 0.f;
    #pragma unroll
    for (int i = 0; i < 8; i++) s2 += sh[i];
    float inv = 1.f / s2;
    for (int j = t; j < L; j += 256) p[j] *= inv;
}

// ---------------- gelu(mlp) -> cat right half ----------------
__global__ void gelu_k() {
    size_t i = (size_t)blockIdx.x * 256 + threadIdx.x;   // exactly L*MLPD threads
    size_t l = i / MLPD, j = i % MLPD;
    float xv = g_h[l * H1 + 3 * HID + j];
    float g = 0.5f * xv * (1.f + tanhf(0.7978845608028654f * (xv + 0.044715f * xv * xv * xv)));
    g_cat[l * CATD + HID + j] = g;
}

// ---------------- final: out = x + gate * (g_o + pl @ proj_up^T) ----------------
__global__ __launch_bounds__(256) void final_k(const float* __restrict__ x,
                                               const float* __restrict__ pu,
                                               float* __restrict__ out)
{
    int l = blockIdx.y;
    int c = blockIdx.x * 256 + threadIdx.x;
    __shared__ float sp[64];
    if (threadIdx.x < 64) sp[threadIdx.x] = g_pl[(size_t)l * 64 + threadIdx.x];
    __syncthreads();

    const float4* ur = (const float4*)(pu + (size_t)c * 64);
    float a = 0.f;
    #pragma unroll
    for (int r = 0; r < 16; r++) {
        float4 u = ur[r];
        a += u.x * sp[4 * r] + u.y * sp[4 * r + 1] + u.z * sp[4 * r + 2] + u.w * sp[4 * r + 3];
    }
    size_t idx = (size_t)l * HID + c;
    float o = g_o[idx] + a;
    out[idx] = x[idx] + g_m[2 * HID + c] * o;
}

// ---------------- launch ----------------
extern "C" void kernel_launch(void* const* d_in, const int* in_sizes, int n_in,
                              void* d_out, int out_size)
{
    const float* x   = (const float*)d_in[0];
    const float* vec = (const float*)d_in[1];
    const float* pe  = (const float*)d_in[2];
    const float* mw  = (const float*)d_in[3];
    const float* mb  = (const float*)d_in[4];
    const float* w1  = (const float*)d_in[5];
    const float* b1  = (const float*)d_in[6];
    const float* w2  = (const float*)d_in[7];
    const float* b2  = (const float*)d_in[8];
    const float* qs  = (const float*)d_in[9];
    const float* ks  = (const float*)d_in[10];
    const float* lqd = (const float*)d_in[11];
    const float* lqu = (const float*)d_in[12];
    const float* lkd = (const float*)d_in[13];
    const float* lku = (const float*)d_in[14];
    const float* lvd = (const float*)d_in[15];
    const float* lvu = (const float*)d_in[16];
    const float* pd  = (const float*)d_in[17];
    const float* pu  = (const float*)d_in[18];
    float* out = (float*)d_out;

    float *xmod, *h, *y1, *q, *k, *v, *S, *cat, *ob, *pl;
    cudaGetSymbolAddress((void**)&xmod, g_xmod);
    cudaGetSymbolAddress((void**)&h,    g_h);
    cudaGetSymbolAddress((void**)&y1,   g_y1);
    cudaGetSymbolAddress((void**)&q,    g_q);
    cudaGetSymbolAddress((void**)&k,    g_k);
    cudaGetSymbolAddress((void**)&v,    g_v);
    cudaGetSymbolAddress((void**)&S,    g_S);
    cudaGetSymbolAddress((void**)&cat,  g_cat);
    cudaGetSymbolAddress((void**)&ob,   g_o);
    cudaGetSymbolAddress((void**)&pl,   g_pl);

    // 1) modulation vector
    silu_k<<<12, 256>>>(vec);
    mod_gemv<<<(3 * HID) / 8, 256>>>(mw, mb);

    // 2) modulated layernorm
    ln_mod_k<<<L, 256>>>(x);

    // 3) big fused GEMM: h = x_mod @ w1^T + b1   (2048 x 21504, K=3072)
    gemm_nt<<<dim3(H1 / 128, L / 128, 1), 256>>>(
        xmod, w1, h, b1, HID, HID, HID, H1, 0LL, 0LL, 0LL, 1.f);

    // 4) lora downs for q,k,v
    lora_down<<<L / 64, 256>>>(xmod, HID, lqd, y1,             32, HID);
    lora_down<<<L / 64, 256>>>(xmod, HID, lkd, y1 + (size_t)L * 32, 32, HID);
    lora_down<<<L / 64, 256>>>(xmod, HID, lvd, y1 + (size_t)2 * L * 32, 32, HID);

    // 5) assemble q,k,v (lora-up add, rms, rope, relayout)
    qkv_finalize<<<dim3(HEADS, L), 128>>>(lqu, lku, lvu, qs, ks, pe);

    // 6) scores = q @ k^T / sqrt(HD), batched over heads
    gemm_nt<<<dim3(L / 128, L / 128, HEADS), 256>>>(
        q, k, S, nullptr, HD, HD, HD, L,
        (long long)L * HD, (long long)L * HD, (long long)L * L,
        0.08838834764831845f);

    // 7) softmax
    softmax_k<<<HEADS * L, 256>>>();

    // 8) attn_out = P @ V  -> cat left half (per-head column offset via sC=128)
    gemm_nt<<<dim3(HD / 128, L / 128, HEADS), 256>>>(
        S, v, cat, nullptr, L, L, L, CATD,
        (long long)L * L, (long long)HD * L, 128LL, 1.f);

    // 9) gelu(mlp) -> cat right half
    gelu_k<<<((size_t)L * MLPD) / 256, 256>>>();

    // 10) out = cat @ w2^T + b2   (2048 x 3072, K=15360)
    gemm_nt<<<dim3(HID / 128, L / 128, 1), 256>>>(
        cat, w2, ob, b2, CATD, CATD, CATD, HID, 0LL, 0LL, 0LL, 1.f);

    // 11) proj lora down (rank 64 as two rank-32 halves)
    lora_down<<<L / 64, 256>>>(cat, CATD, pd,                       pl,      64, CATD);
    lora_down<<<L / 64, 256>>>(cat, CATD, pd + (size_t)32 * CATD,   pl + 32, 64, CATD);

    // 12) final residual: out = x + gate * (g_o + pl @ proj_up^T)
    final_k<<<dim3(HID / 256, L), 256>>>(x, pu, out);
}

// round 3
// speedup vs baseline: 2.1182x; 2.1182x over previous
#include <cuda_runtime.h>
#include <cuda_bf16.h>
#include <math.h>
#include <stdint.h>

#define L 2048
#define HID 3072
#define HEADS 24
#define HD 128
#define MLPD 12288
#define H1 21504    // 3*HID + MLP
#define CATD 15360  // HID + MLP

// ---------------- scratch (device globals; no allocation allowed) ----------------
__device__ float g_sv[HID];
__device__ float g_m[3 * HID];
__device__ float g_xmod[(size_t)L * HID];
__device__ float g_h[(size_t)L * H1];
__device__ float g_y1[3 * (size_t)L * 32];
__device__ float g_S[(size_t)HEADS * L * L];      // fp32 scores
__device__ float g_cat[(size_t)L * CATD];
__device__ float g_o[(size_t)L * HID];
__device__ float g_pl[(size_t)L * 64];

// split bf16 [hi(K) | lo(K)] buffers
__device__ __nv_bfloat16 g_xmod2[(size_t)L * 2 * HID];
__device__ __nv_bfloat16 g_w12[(size_t)H1 * 2 * HID];
__device__ __nv_bfloat16 g_w22[(size_t)HID * 2 * CATD];
__device__ __nv_bfloat16 g_cat2[(size_t)L * 2 * CATD];
__device__ __nv_bfloat16 g_q2[(size_t)HEADS * L * 2 * HD];
__device__ __nv_bfloat16 g_k2[(size_t)HEADS * L * 2 * HD];
__device__ __nv_bfloat16 g_v2[(size_t)HEADS * HD * 2 * L];
__device__ __nv_bfloat16 g_S2[(size_t)HEADS * L * 2 * L];

// ================= helpers =================
__device__ __forceinline__ uint32_t smem_u32(const void* p) {
    uint32_t a;
    asm("{ .reg .u64 t; cvta.to.shared.u64 t, %1; cvt.u32.u64 %0, t; }" : "=r"(a) : "l"(p));
    return a;
}
__device__ __forceinline__ void cpasync16(uint32_t dst, const void* src) {
    asm volatile("cp.async.cg.shared.global [%0], [%1], 16;" :: "r"(dst), "l"(src) : "memory");
}
__device__ __forceinline__ void ldsm4(uint32_t& r0, uint32_t& r1, uint32_t& r2, uint32_t& r3,
                                      uint32_t addr) {
    asm volatile("ldmatrix.sync.aligned.m8n8.x4.shared.b16 {%0,%1,%2,%3}, [%4];"
                 : "=r"(r0), "=r"(r1), "=r"(r2), "=r"(r3) : "r"(addr));
}
__device__ __forceinline__ void mma16816(float* d, const uint32_t* a, const uint32_t* b) {
    asm volatile(
        "mma.sync.aligned.m16n8k16.row.col.f32.bf16.bf16.f32 "
        "{%0,%1,%2,%3}, {%4,%5,%6,%7}, {%8,%9}, {%0,%1,%2,%3};"
        : "+f"(d[0]), "+f"(d[1]), "+f"(d[2]), "+f"(d[3])
        : "r"(a[0]), "r"(a[1]), "r"(a[2]), "r"(a[3]), "r"(b[0]), "r"(b[1]));
}
__device__ __forceinline__ void split1(float x, __nv_bfloat16& h, __nv_bfloat16& l) {
    h = __float2bfloat16(x);
    l = __float2bfloat16(x - __bfloat162float(h));
}

// ================= split-bf16 3-term NT GEMM on mma.sync =================
// C = scale * (A @ B^T) + bias.
// A2: (M, 2K) bf16 [hi|lo], lda2 row stride (bf16). B2: (N, 2K) bf16. C: (M,N) fp32.
// BM=128, BN in {128,256}. K % 64 == 0. 8 warps as 2(m) x 4(n); warp tile 64 x BN/4.
template <int BN, bool HASBIAS>
__global__ __launch_bounds__(256, 1) void gemm_bf3(
    const __nv_bfloat16* __restrict__ A2, const __nv_bfloat16* __restrict__ B2,
    float* __restrict__ C, const float* __restrict__ bias,
    int K, int lda2, int ldb2, int ldc,
    long long sA, long long sB, long long sC, float scale)
{
    constexpr int BM = 128;
    constexpr int WN = BN / 4;          // 64 or 32
    constexpr int NT = WN / 8;          // n-tiles per warp: 8 or 4
    constexpr int ABYTES = BM * 128;    // 16KB
    constexpr int BBYTES = BN * 128;
    constexpr int STAGE = ABYTES + BBYTES;

    extern __shared__ char smraw[];
    uint32_t s0 = smem_u32(smraw);

    A2 += (size_t)blockIdx.z * sA;
    B2 += (size_t)blockIdx.z * sB;
    C  += (size_t)blockIdx.z * sC;

    const int t = threadIdx.x, w = t >> 5, lane = t & 31;
    const int wm = w & 1, wn = w >> 1;
    const int m0 = blockIdx.x * BM, n0 = blockIdx.y * BN;

    const int kdiv = K >> 6;
    const int nc = 3 * kdiv;

    auto issue = [&](int c, int stg) {
        int term = c / kdiv, kc = c - term * kdiv;
        int aoff = ((term == 2) ? K : 0) + kc * 64;
        int boff = ((term == 1) ? K : 0) + kc * 64;
        uint32_t ab = s0 + (uint32_t)stg * STAGE;
        const __nv_bfloat16* Ap = A2 + (size_t)m0 * lda2 + aoff;
        #pragma unroll
        for (int i = 0; i < BM / 32; i++) {
            int f = t + i * 256, row = f >> 3, q = f & 7;
            uint32_t dst = ab + (uint32_t)row * 128u + ((uint32_t)(q ^ (row & 7)) << 4);
            cpasync16(dst, Ap + (size_t)row * lda2 + q * 8);
        }
        uint32_t bb = ab + ABYTES;
        const __nv_bfloat16* Bp = B2 + (size_t)n0 * ldb2 + boff;
        #pragma unroll
        for (int i = 0; i < BN / 32; i++) {
            int f = t + i * 256, row = f >> 3, q = f & 7;
            uint32_t dst = bb + (uint32_t)row * 128u + ((uint32_t)(q ^ (row & 7)) << 4);
            cpasync16(dst, Bp + (size_t)row * ldb2 + q * 8);
        }
        asm volatile("cp.async.commit_group;" ::: "memory");
    };

    float acc[4][NT][4];
    #pragma unroll
    for (int i = 0; i < 4; i++)
        #pragma unroll
        for (int j = 0; j < NT; j++)
            #pragma unroll
            for (int q = 0; q < 4; q++) acc[i][j][q] = 0.f;

    issue(0, 0);
    issue(1, 1);

    for (int c = 0; c < nc; c++) {
        asm volatile("cp.async.wait_group 1;" ::: "memory");
        __syncthreads();
        if (c + 2 < nc) issue(c + 2, (c + 2) % 3);

        uint32_t ab = s0 + (uint32_t)(c % 3) * STAGE;
        uint32_t bb = ab + ABYTES;

        #pragma unroll
        for (int s = 0; s < 4; s++) {
            uint32_t Af[4][4];
            #pragma unroll
            for (int mt = 0; mt < 4; mt++) {
                int row = wm * 64 + mt * 16 + (lane & 15);
                uint32_t q0 = (uint32_t)(s * 2 + (lane >> 4));
                uint32_t addr = ab + (uint32_t)row * 128u + ((q0 ^ (uint32_t)(row & 7)) << 4);
                ldsm4(Af[mt][0], Af[mt][1], Af[mt][2], Af[mt][3], addr);
            }
            uint32_t Bf[NT][2];
            #pragma unroll
            for (int np = 0; np < NT / 2; np++) {
                int row = wn * WN + np * 16 + ((lane >> 4) << 3) + (lane & 7);
                uint32_t q0 = (uint32_t)(s * 2 + ((lane >> 3) & 1));
                uint32_t addr = bb + (uint32_t)row * 128u + ((q0 ^ (uint32_t)(row & 7)) << 4);
                ldsm4(Bf[2 * np][0], Bf[2 * np][1], Bf[2 * np + 1][0], Bf[2 * np + 1][1], addr);
            }
            #pragma unroll
            for (int mt = 0; mt < 4; mt++)
                #pragma unroll
                for (int nt = 0; nt < NT; nt++)
                    mma16816(acc[mt][nt], Af[mt], Bf[nt]);
        }
        __syncthreads();
    }

    // epilogue
    #pragma unroll
    for (int mt = 0; mt < 4; mt++) {
        int row = m0 + wm * 64 + mt * 16 + (lane >> 2);
        #pragma unroll
        for (int nt = 0; nt < NT; nt++) {
            int col = n0 + wn * WN + nt * 8 + (lane & 3) * 2;
            float b0 = 0.f, b1 = 0.f;
            if (HASBIAS) { b0 = bias[col]; b1 = bias[col + 1]; }
            float* c0 = C + (size_t)row * ldc + col;
            float* c1 = C + (size_t)(row + 8) * ldc + col;
            c0[0] = acc[mt][nt][0] * scale + b0;
            c0[1] = acc[mt][nt][1] * scale + b1;
            c1[0] = acc[mt][nt][2] * scale + b0;
            c1[1] = acc[mt][nt][3] * scale + b1;
        }
    }
}

// ================= fp32 -> [hi|lo] bf16 split conversion =================
__global__ void conv_split(const float* __restrict__ src, __nv_bfloat16* __restrict__ dst,
                           int K, long long n4) {
    long long i = (long long)blockIdx.x * 256 + threadIdx.x;
    if (i >= n4) return;
    long long e = i * 4;
    long long r = e / K;
    int c = (int)(e - r * K);
    float4 v = *(const float4*)(src + e);
    __nv_bfloat16 h0, h1, h2, h3, l0, l1, l2, l3;
    split1(v.x, h0, l0); split1(v.y, h1, l1);
    split1(v.z, h2, l2); split1(v.w, h3, l3);
    __nv_bfloat16* dh = dst + r * (2LL * K) + c;
    __nv_bfloat16* dl = dh + K;
    *(__nv_bfloat162*)(dh)     = __nv_bfloat162(h0, h1);
    *(__nv_bfloat162*)(dh + 2) = __nv_bfloat162(h2, h3);
    *(__nv_bfloat162*)(dl)     = __nv_bfloat162(l0, l1);
    *(__nv_bfloat162*)(dl + 2) = __nv_bfloat162(l2, l3);
}

// ================= small kernels =================
__global__ void silu_k(const float* __restrict__ vec) {
    int i = blockIdx.x * 256 + threadIdx.x;
    if (i < HID) { float v = vec[i]; g_sv[i] = v / (1.f + expf(-v)); }
}

__global__ __launch_bounds__(256) void mod_gemv(const float* __restrict__ W,
                                                const float* __restrict__ b) {
    int o = blockIdx.x * 8 + (threadIdx.x >> 5);
    int lane = threadIdx.x & 31;
    const float* w = W + (size_t)o * HID;
    float acc = 0.f;
    for (int k = lane; k < HID; k += 32) acc += g_sv[k] * w[k];
    #pragma unroll
    for (int s = 16; s; s >>= 1) acc += __shfl_xor_sync(0xffffffffu, acc, s);
    if (lane == 0) g_m[o] = acc + b[o];
}

__global__ __launch_bounds__(256) void ln_mod_k(const float* __restrict__ x) {
    int l = blockIdx.x, t = threadIdx.x;
    const float* xr = x + (size_t)l * HID;
    float s = 0.f, s2 = 0.f;
    for (int j = t; j < HID; j += 256) { float v = xr[j]; s += v; s2 += v * v; }
    __shared__ float sh[16];
    #pragma unroll
    for (int o = 16; o; o >>= 1) {
        s  += __shfl_xor_sync(0xffffffffu, s, o);
        s2 += __shfl_xor_sync(0xffffffffu, s2, o);
    }
    if ((t & 31) == 0) { sh[t >> 5] = s; sh[8 + (t >> 5)] = s2; }
    __syncthreads();
    float ts = 0.f, ts2 = 0.f;
    #pragma unroll
    for (int i = 0; i < 8; i++) { ts += sh[i]; ts2 += sh[8 + i]; }
    float mu = ts * (1.f / HID);
    float var = ts2 * (1.f / HID) - mu * mu;
    float r = rsqrtf(var + 1e-6f);
    for (int j = t; j < HID; j += 256) {
        float v = (xr[j] - mu) * r;
        g_xmod[(size_t)l * HID + j] = (1.f + g_m[HID + j]) * v + g_m[j];
    }
}

__global__ __launch_bounds__(256) void lora_down(
    const float* __restrict__ X, int ldx, const float* __restrict__ D,
    float* __restrict__ Y, int ldy, int K)
{
    __shared__ float xs[64][64];
    __shared__ float ds[64][32];
    int t = threadIdx.x;
    int m0 = blockIdx.x * 64;
    int tx = t & 31, ty = t >> 5;
    int xrow = t >> 2, xf4 = t & 3;
    int drow = t >> 3, df4 = t & 7;
    float acc[8] = {};

    for (int k0 = 0; k0 < K; k0 += 64) {
        #pragma unroll
        for (int j = 0; j < 4; j++) {
            int kk = (xf4 + 4 * j) * 4;
            float4 vx = *(const float4*)(X + (size_t)(m0 + xrow) * ldx + k0 + kk);
            xs[kk][xrow] = vx.x; xs[kk + 1][xrow] = vx.y;
            xs[kk + 2][xrow] = vx.z; xs[kk + 3][xrow] = vx.w;
        }
        #pragma unroll
        for (int j = 0; j < 2; j++) {
            int kk = (df4 + 8 * j) * 4;
            float4 vd = *(const float4*)(D + (size_t)drow * K + k0 + kk);
            ds[kk][drow] = vd.x; ds[kk + 1][drow] = vd.y;
            ds[kk + 2][drow] = vd.z; ds[kk + 3][drow] = vd.w;
        }
        __syncthreads();
        #pragma unroll
        for (int kk = 0; kk < 64; kk++) {
            float dv = ds[kk][tx];
            #pragma unroll
            for (int i = 0; i < 8; i++) acc[i] += xs[kk][ty * 8 + i] * dv;
        }
        __syncthreads();
    }
    #pragma unroll
    for (int i = 0; i < 8; i++)
        Y[(size_t)(m0 + ty * 8 + i) * ldy + tx] = acc[i];
}

__global__ __launch_bounds__(128) void qkv_finalize(
    const float* __restrict__ upq, const float* __restrict__ upk,
    const float* __restrict__ upv, const float* __restrict__ q_scale,
    const float* __restrict__ k_scale, const float* __restrict__ pe)
{
    int head = blockIdx.x, l = blockIdx.y, d = threadIdx.x;
    int col = head * HD + d;

    __shared__ float yq[32], yk[32], yv[32];
    __shared__ float sq[128], sk[128];
    __shared__ float wq[4], wk[4];

    if (d < 32)       yq[d]      = g_y1[(size_t)l * 32 + d];
    else if (d < 64)  yk[d - 32] = g_y1[(size_t)(L + l) * 32 + (d - 32)];
    else if (d < 96)  yv[d - 64] = g_y1[(size_t)(2 * L + l) * 32 + (d - 64)];
    __syncthreads();

    size_t hb = (size_t)l * H1;
    float qv = g_h[hb + col];
    float kv = g_h[hb + HID + col];
    float vv = g_h[hb + 2 * HID + col];

    {
        const float4* u = (const float4*)(upq + (size_t)col * 32);
        float a = 0.f;
        #pragma unroll
        for (int r = 0; r < 8; r++) {
            float4 t4 = u[r];
            a += t4.x * yq[4 * r] + t4.y * yq[4 * r + 1] + t4.z * yq[4 * r + 2] + t4.w * yq[4 * r + 3];
        }
        qv += a;
    }
    {
        const float4* u = (const float4*)(upk + (size_t)col * 32);
        float a = 0.f;
        #pragma unroll
        for (int r = 0; r < 8; r++) {
            float4 t4 = u[r];
            a += t4.x * yk[4 * r] + t4.y * yk[4 * r + 1] + t4.z * yk[4 * r + 2] + t4.w * yk[4 * r + 3];
        }
        kv += a;
    }
    {
        const float4* u = (const float4*)(upv + (size_t)col * 32);
        float a = 0.f;
        #pragma unroll
        for (int r = 0; r < 8; r++) {
            float4 t4 = u[r];
            a += t4.x * yv[4 * r] + t4.y * yv[4 * r + 1] + t4.z * yv[4 * r + 2] + t4.w * yv[4 * r + 3];
        }
        vv += a;
    }

    sq[d] = qv; sk[d] = kv;
    float aq = qv * qv, ak = kv * kv;
    #pragma unroll
    for (int o = 16; o; o >>= 1) {
        aq += __shfl_xor_sync(0xffffffffu, aq, o);
        ak += __shfl_xor_sync(0xffffffffu, ak, o);
    }
    if ((d & 31) == 0) { wq[d >> 5] = aq; wk[d >> 5] = ak; }
    __syncthreads();

    float rq = rsqrtf((wq[0] + wq[1] + wq[2] + wq[3]) * (1.f / HD) + 1e-6f);
    float rk = rsqrtf((wk[0] + wk[1] + wk[2] + wk[3]) * (1.f / HD) + 1e-6f);

    int e = d & ~1, o_ = d | 1;
    float q0 = sq[e]  * rq * q_scale[e];
    float q1 = sq[o_] * rq * q_scale[o_];
    float k0 = sk[e]  * rk * k_scale[e];
    float k1 = sk[o_] * rk * k_scale[o_];

    const float* p = pe + ((size_t)l * 64 + (d >> 1)) * 4;
    float qo = (d & 1) ? (p[2] * q0 + p[3] * q1) : (p[0] * q0 + p[1] * q1);
    float ko = (d & 1) ? (p[2] * k0 + p[3] * k1) : (p[0] * k0 + p[1] * k1);

    __nv_bfloat16 h, lo;
    size_t qb = ((size_t)head * L + l) * (2 * HD);
    split1(qo, h, lo); g_q2[qb + d] = h; g_q2[qb + HD + d] = lo;
    split1(ko, h, lo); g_k2[qb + d] = h; g_k2[qb + HD + d] = lo;
    size_t vb = ((size_t)head * HD + d) * (2 * L);
    split1(vv, h, lo); g_v2[vb + l] = h; g_v2[vb + L + l] = lo;
}

// softmax: fp32 scores -> split bf16 probs
__global__ __launch_bounds__(256) void softmax_k() {
    const float* p = g_S + (size_t)blockIdx.x * L;
    __nv_bfloat16* o = g_S2 + (size_t)blockIdx.x * (2 * L);
    int t = threadIdx.x;
    __shared__ float buf[L];
    __shared__ float sh[8];

    float mx = -1e30f;
    for (int j = t; j < L; j += 256) { float v = p[j]; buf[j] = v; mx = fmaxf(mx, v); }
    #pragma unroll
    for (int s = 16; s; s >>= 1) mx = fmaxf(mx, __shfl_xor_sync(0xffffffffu, mx, s));
    if ((t & 31) == 0) sh[t >> 5] = mx;
    __syncthreads();
    float m2 = sh[0];
    #pragma unroll
    for (int i = 1; i < 8; i++) m2 = fmaxf(m2, sh[i]);

    float sum = 0.f;
    for (int j = t; j < L; j += 256) {
        float e = __expf(buf[j] - m2);
        buf[j] = e;
        sum += e;
    }
    #pragma unroll
    for (int s = 16; s; s >>= 1) sum += __shfl_xor_sync(0xffffffffu, sum, s);
    if ((t & 31) == 0) sh[t >> 5] = sum;
    __syncthreads();
    float s2 = 0.f;
    #pragma unroll
    for (int i = 0; i < 8; i++) s2 += sh[i];
    float inv = 1.f / s2;
    for (int j = t; j < L; j += 256) {
        float v = buf[j] * inv;
        __nv_bfloat16 h, lo;
        split1(v, h, lo);
        o[j] = h; o[L + j] = lo;
    }
}

__global__ void gelu_k() {
    size_t i = (size_t)blockIdx.x * 256 + threadIdx.x;
    size_t l = i / MLPD, j = i % MLPD;
    float xv = g_h[l * H1 + 3 * HID + j];
    float g = 0.5f * xv * (1.f + tanhf(0.7978845608028654f * (xv + 0.044715f * xv * xv * xv)));
    g_cat[l * CATD + HID + j] = g;
}

__global__ __launch_bounds__(256) void final_k(const float* __restrict__ x,
                                               const float* __restrict__ pu,
                                               float* __restrict__ out)
{
    int l = blockIdx.y;
    int c = blockIdx.x * 256 + threadIdx.x;
    __shared__ float sp[64];
    if (threadIdx.x < 64) sp[threadIdx.x] = g_pl[(size_t)l * 64 + threadIdx.x];
    __syncthreads();

    const float4* ur = (const float4*)(pu + (size_t)c * 64);
    float a = 0.f;
    #pragma unroll
    for (int r = 0; r < 16; r++) {
        float4 u = ur[r];
        a += u.x * sp[4 * r] + u.y * sp[4 * r + 1] + u.z * sp[4 * r + 2] + u.w * sp[4 * r + 3];
    }
    size_t idx = (size_t)l * HID + c;
    float o = g_o[idx] + a;
    out[idx] = x[idx] + g_m[2 * HID + c] * o;
}

// ================= launch =================
extern "C" void kernel_launch(void* const* d_in, const int* in_sizes, int n_in,
                              void* d_out, int out_size)
{
    const float* x   = (const float*)d_in[0];
    const float* vec = (const float*)d_in[1];
    const float* pe  = (const float*)d_in[2];
    const float* mw  = (const float*)d_in[3];
    const float* mb  = (const float*)d_in[4];
    const float* w1  = (const float*)d_in[5];
    const float* b1  = (const float*)d_in[6];
    const float* w2  = (const float*)d_in[7];
    const float* b2  = (const float*)d_in[8];
    const float* qs  = (const float*)d_in[9];
    const float* ks  = (const float*)d_in[10];
    const float* lqd = (const float*)d_in[11];
    const float* lqu = (const float*)d_in[12];
    const float* lkd = (const float*)d_in[13];
    const float* lku = (const float*)d_in[14];
    const float* lvd = (const float*)d_in[15];
    const float* lvu = (const float*)d_in[16];
    const float* pd  = (const float*)d_in[17];
    const float* pu  = (const float*)d_in[18];
    float* out = (float*)d_out;

    float *xmod, *h, *y1, *S, *cat, *ob, *pl;
    __nv_bfloat16 *xmod2, *w12, *w22, *cat2, *q2, *k2, *v2, *S2;
    cudaGetSymbolAddress((void**)&xmod,  g_xmod);
    cudaGetSymbolAddress((void**)&h,     g_h);
    cudaGetSymbolAddress((void**)&y1,    g_y1);
    cudaGetSymbolAddress((void**)&S,     g_S);
    cudaGetSymbolAddress((void**)&cat,   g_cat);
    cudaGetSymbolAddress((void**)&ob,    g_o);
    cudaGetSymbolAddress((void**)&pl,    g_pl);
    cudaGetSymbolAddress((void**)&xmod2, g_xmod2);
    cudaGetSymbolAddress((void**)&w12,   g_w12);
    cudaGetSymbolAddress((void**)&w22,   g_w22);
    cudaGetSymbolAddress((void**)&cat2,  g_cat2);
    cudaGetSymbolAddress((void**)&q2,    g_q2);
    cudaGetSymbolAddress((void**)&k2,    g_k2);
    cudaGetSymbolAddress((void**)&v2,    g_v2);
    cudaGetSymbolAddress((void**)&S2,    g_S2);

    const int SM256 = 3 * (128 + 256) * 128;   // 147456
    const int SM128 = 3 * (128 + 128) * 128;   // 98304
    cudaFuncSetAttribute(gemm_bf3<256, true>,  cudaFuncAttributeMaxDynamicSharedMemorySize, SM256);
    cudaFuncSetAttribute(gemm_bf3<256, false>, cudaFuncAttributeMaxDynamicSharedMemorySize, SM256);
    cudaFuncSetAttribute(gemm_bf3<128, false>, cudaFuncAttributeMaxDynamicSharedMemorySize, SM128);

    // 1) modulation vector
    silu_k<<<12, 256>>>(vec);
    mod_gemv<<<(3 * HID) / 8, 256>>>(mw, mb);

    // 2) modulated layernorm
    ln_mod_k<<<L, 256>>>(x);

    // 3) split conversions for big GEMM 1
    conv_split<<<(int)(((size_t)L * HID / 4 + 255) / 256), 256>>>(xmod, xmod2, HID, (size_t)L * HID / 4);
    conv_split<<<(int)(((size_t)H1 * HID / 4 + 255) / 256), 256>>>(w1, w12, HID, (size_t)H1 * HID / 4);

    // 4) h = x_mod @ w1^T + b1
    gemm_bf3<256, true><<<dim3(L / 128, H1 / 256, 1), 256, SM256>>>(
        xmod2, w12, h, b1, HID, 2 * HID, 2 * HID, H1, 0LL, 0LL, 0LL, 1.f);

    // 5) lora downs (fp32)
    lora_down<<<L / 64, 256>>>(xmod, HID, lqd, y1,                      32, HID);
    lora_down<<<L / 64, 256>>>(xmod, HID, lkd, y1 + (size_t)L * 32,     32, HID);
    lora_down<<<L / 64, 256>>>(xmod, HID, lvd, y1 + (size_t)2 * L * 32, 32, HID);

    // 6) assemble q,k,v -> split bf16
    qkv_finalize<<<dim3(HEADS, L), 128>>>(lqu, lku, lvu, qs, ks, pe);

    // 7) scores = q @ k^T / sqrt(HD)
    gemm_bf3<256, false><<<dim3(L / 128, L / 256, HEADS), 256, SM256>>>(
        q2, k2, S, nullptr, HD, 2 * HD, 2 * HD, L,
        (long long)L * 2 * HD, (long long)L * 2 * HD, (long long)L * L,
        0.08838834764831845f);

    // 8) softmax -> split bf16 probs
    softmax_k<<<HEADS * L, 256>>>();

    // 9) attn_out = P @ V -> cat left half
    gemm_bf3<128, false><<<dim3(L / 128, 1, HEADS), 256, SM128>>>(
        S2, v2, cat, nullptr, L, 2 * L, 2 * L, CATD,
        (long long)L * 2 * L, (long long)HD * 2 * L, 128LL, 1.f);

    // 10) gelu(mlp) -> cat right half
    gelu_k<<<(int)(((size_t)L * MLPD) / 256), 256>>>();

    // 11) split conversions for big GEMM 2
    conv_split<<<(int)(((size_t)L * CATD / 4 + 255) / 256), 256>>>(cat, cat2, CATD, (size_t)L * CATD / 4);
    conv_split<<<(int)(((size_t)HID * CATD / 4 + 255) / 256), 256>>>(w2, w22, CATD, (size_t)HID * CATD / 4);

    // 12) out_lin = cat @ w2^T + b2
    gemm_bf3<256, true><<<dim3(L / 128, HID / 256, 1), 256, SM256>>>(
        cat2, w22, ob, b2, CATD, 2 * CATD, 2 * CATD, HID, 0LL, 0LL, 0LL, 1.f);

    // 13) proj lora down (rank 64 as two rank-32 halves, fp32)
    lora_down<<<L / 64, 256>>>(cat, CATD, pd,                     pl,      64, CATD);
    lora_down<<<L / 64, 256>>>(cat, CATD, pd + (size_t)32 * CATD, pl + 32, 64, CATD);

    // 14) final residual
    final_k<<<dim3(HID / 256, L), 256>>>(x, pu, out);
}

// round 4
// speedup vs baseline: 3.5822x; 1.6911x over previous
#include <cuda_runtime.h>
#include <cuda_fp16.h>
#include <math.h>
#include <stdint.h>

#define L 2048
#define HID 3072
#define HEADS 24
#define HD 128
#define MLPD 12288
#define H1 21504    // 3*HID + MLP
#define CATD 15360  // HID + MLP

// ---------------- scratch (device globals; no allocation allowed) ----------------
__device__ float g_sv[HID];
__device__ float g_m[3 * HID];
__device__ float g_xmod[(size_t)L * HID];
__device__ float g_h[(size_t)L * H1];
__device__ float g_y1[3 * (size_t)L * 32];
__device__ float g_S[(size_t)HEADS * L * L];      // fp32 scores
__device__ float g_cat[(size_t)L * CATD];
__device__ float g_o[(size_t)L * HID];
__device__ float g_pl[(size_t)L * 64];

// fp16 single-precision-pass buffers
__device__ __half g_xmod2[(size_t)L * HID];
__device__ __half g_w12[(size_t)H1 * HID];
__device__ __half g_w22[(size_t)HID * CATD];
__device__ __half g_cat2[(size_t)L * CATD];
__device__ __half g_q2[(size_t)HEADS * L * HD];
__device__ __half g_k2[(size_t)HEADS * L * HD];
__device__ __half g_v2[(size_t)HEADS * HD * L];   // [h][d][l]
__device__ __half g_S2[(size_t)HEADS * L * L];    // probs

// ================= helpers =================
__device__ __forceinline__ uint32_t smem_u32(const void* p) {
    uint32_t a;
    asm("{ .reg .u64 t; cvta.to.shared.u64 t, %1; cvt.u32.u64 %0, t; }" : "=r"(a) : "l"(p));
    return a;
}
__device__ __forceinline__ void cpasync16(uint32_t dst, const void* src) {
    asm volatile("cp.async.cg.shared.global [%0], [%1], 16;" :: "r"(dst), "l"(src) : "memory");
}
__device__ __forceinline__ void ldsm4(uint32_t& r0, uint32_t& r1, uint32_t& r2, uint32_t& r3,
                                      uint32_t addr) {
    asm volatile("ldmatrix.sync.aligned.m8n8.x4.shared.b16 {%0,%1,%2,%3}, [%4];"
                 : "=r"(r0), "=r"(r1), "=r"(r2), "=r"(r3) : "r"(addr));
}
__device__ __forceinline__ void mma16816(float* d, const uint32_t* a, const uint32_t* b) {
    asm volatile(
        "mma.sync.aligned.m16n8k16.row.col.f32.f16.f16.f32 "
        "{%0,%1,%2,%3}, {%4,%5,%6,%7}, {%8,%9}, {%0,%1,%2,%3};"
        : "+f"(d[0]), "+f"(d[1]), "+f"(d[2]), "+f"(d[3])
        : "r"(a[0]), "r"(a[1]), "r"(a[2]), "r"(a[3]), "r"(b[0]), "r"(b[1]));
}

// ================= fp16 NT GEMM on mma.sync =================
// C = scale * (A @ B^T) + bias.
// A2: (M,K) fp16 lda; B2: (N,K) fp16 ldb; C: (M,N) fp32 ldc.
// BM=128, BN in {128,256}. K % 64 == 0. 8 warps as 2(m) x 4(n).
template <int BN, bool HASBIAS>
__global__ __launch_bounds__(256, 1) void gemm_hf(
    const __half* __restrict__ A2, const __half* __restrict__ B2,
    float* __restrict__ C, const float* __restrict__ bias,
    int K, int lda, int ldb, int ldc,
    long long sA, long long sB, long long sC, float scale)
{
    constexpr int BM = 128;
    constexpr int WN = BN / 4;          // 64 or 32
    constexpr int NT = WN / 8;          // 8 or 4
    constexpr int ABYTES = BM * 128;    // 16KB
    constexpr int BBYTES = BN * 128;
    constexpr int STAGE = ABYTES + BBYTES;

    extern __shared__ char smraw[];
    uint32_t s0 = smem_u32(smraw);

    A2 += (size_t)blockIdx.z * sA;
    B2 += (size_t)blockIdx.z * sB;
    C  += (size_t)blockIdx.z * sC;

    const int t = threadIdx.x, w = t >> 5, lane = t & 31;
    const int wm = w & 1, wn = w >> 1;
    const int m0 = blockIdx.x * BM, n0 = blockIdx.y * BN;

    const int nc = K >> 6;

    auto issue = [&](int c, int stg) {
        uint32_t ab = s0 + (uint32_t)stg * STAGE;
        const __half* Ap = A2 + (size_t)m0 * lda + c * 64;
        #pragma unroll
        for (int i = 0; i < BM / 32; i++) {
            int f = t + i * 256, row = f >> 3, q = f & 7;
            uint32_t dst = ab + (uint32_t)row * 128u + ((uint32_t)(q ^ (row & 7)) << 4);
            cpasync16(dst, Ap + (size_t)row * lda + q * 8);
        }
        uint32_t bb = ab + ABYTES;
        const __half* Bp = B2 + (size_t)n0 * ldb + c * 64;
        #pragma unroll
        for (int i = 0; i < BN / 32; i++) {
            int f = t + i * 256, row = f >> 3, q = f & 7;
            uint32_t dst = bb + (uint32_t)row * 128u + ((uint32_t)(q ^ (row & 7)) << 4);
            cpasync16(dst, Bp + (size_t)row * ldb + q * 8);
        }
        asm volatile("cp.async.commit_group;" ::: "memory");
    };

    float acc[4][NT][4];
    #pragma unroll
    for (int i = 0; i < 4; i++)
        #pragma unroll
        for (int j = 0; j < NT; j++)
            #pragma unroll
            for (int q = 0; q < 4; q++) acc[i][j][q] = 0.f;

    issue(0, 0);
    if (nc > 1) issue(1, 1);

    for (int c = 0; c < nc; c++) {
        if (c + 2 < nc) {
            issue(c + 2, (c + 2) % 3);
            asm volatile("cp.async.wait_group 2;" ::: "memory");
        } else if (c + 1 < nc) {
            asm volatile("cp.async.wait_group 1;" ::: "memory");
        } else {
            asm volatile("cp.async.wait_group 0;" ::: "memory");
        }
        __syncthreads();

        uint32_t ab = s0 + (uint32_t)(c % 3) * STAGE;
        uint32_t bb = ab + ABYTES;

        #pragma unroll
        for (int s = 0; s < 4; s++) {
            uint32_t Af[4][4];
            #pragma unroll
            for (int mt = 0; mt < 4; mt++) {
                int row = wm * 64 + mt * 16 + (lane & 15);
                uint32_t q0 = (uint32_t)(s * 2 + (lane >> 4));
                uint32_t addr = ab + (uint32_t)row * 128u + ((q0 ^ (uint32_t)(row & 7)) << 4);
                ldsm4(Af[mt][0], Af[mt][1], Af[mt][2], Af[mt][3], addr);
            }
            uint32_t Bf[NT][2];
            #pragma unroll
            for (int np = 0; np < NT / 2; np++) {
                int row = wn * WN + np * 16 + ((lane >> 4) << 3) + (lane & 7);
                uint32_t q0 = (uint32_t)(s * 2 + ((lane >> 3) & 1));
                uint32_t addr = bb + (uint32_t)row * 128u + ((q0 ^ (uint32_t)(row & 7)) << 4);
                ldsm4(Bf[2 * np][0], Bf[2 * np][1], Bf[2 * np + 1][0], Bf[2 * np + 1][1], addr);
            }
            #pragma unroll
            for (int mt = 0; mt < 4; mt++)
                #pragma unroll
                for (int nt = 0; nt < NT; nt++)
                    mma16816(acc[mt][nt], Af[mt], Bf[nt]);
        }
        __syncthreads();
    }

    #pragma unroll
    for (int mt = 0; mt < 4; mt++) {
        int row = m0 + wm * 64 + mt * 16 + (lane >> 2);
        #pragma unroll
        for (int nt = 0; nt < NT; nt++) {
            int col = n0 + wn * WN + nt * 8 + (lane & 3) * 2;
            float b0 = 0.f, b1 = 0.f;
            if (HASBIAS) { b0 = bias[col]; b1 = bias[col + 1]; }
            float* c0 = C + (size_t)row * ldc + col;
            float* c1 = C + (size_t)(row + 8) * ldc + col;
            c0[0] = acc[mt][nt][0] * scale + b0;
            c0[1] = acc[mt][nt][1] * scale + b1;
            c1[0] = acc[mt][nt][2] * scale + b0;
            c1[1] = acc[mt][nt][3] * scale + b1;
        }
    }
}

// ================= fp32 -> fp16 streaming convert (8 elems/thread) =================
__global__ void conv_half(const float* __restrict__ src, __half* __restrict__ dst,
                          long long n8) {
    long long i = (long long)blockIdx.x * 256 + threadIdx.x;
    if (i >= n8) return;
    const float4* s = (const float4*)(src + i * 8);
    float4 a = s[0], b = s[1];
    __half2 h0 = __floats2half2_rn(a.x, a.y);
    __half2 h1 = __floats2half2_rn(a.z, a.w);
    __half2 h2 = __floats2half2_rn(b.x, b.y);
    __half2 h3 = __floats2half2_rn(b.z, b.w);
    uint4 o;
    o.x = *(uint32_t*)&h0; o.y = *(uint32_t*)&h1;
    o.z = *(uint32_t*)&h2; o.w = *(uint32_t*)&h3;
    ((uint4*)dst)[i] = o;
}

// ================= small kernels =================
__global__ void silu_k(const float* __restrict__ vec) {
    int i = blockIdx.x * 256 + threadIdx.x;
    if (i < HID) { float v = vec[i]; g_sv[i] = v / (1.f + expf(-v)); }
}

__global__ __launch_bounds__(256) void mod_gemv(const float* __restrict__ W,
                                                const float* __restrict__ b) {
    int o = blockIdx.x * 8 + (threadIdx.x >> 5);
    int lane = threadIdx.x & 31;
    const float* w = W + (size_t)o * HID;
    float acc = 0.f;
    for (int k = lane; k < HID; k += 32) acc += g_sv[k] * w[k];
    #pragma unroll
    for (int s = 16; s; s >>= 1) acc += __shfl_xor_sync(0xffffffffu, acc, s);
    if (lane == 0) g_m[o] = acc + b[o];
}

__global__ __launch_bounds__(256) void ln_mod_k(const float* __restrict__ x) {
    int l = blockIdx.x, t = threadIdx.x;
    const float* xr = x + (size_t)l * HID;
    float s = 0.f, s2 = 0.f;
    for (int j = t; j < HID; j += 256) { float v = xr[j]; s += v; s2 += v * v; }
    __shared__ float sh[16];
    #pragma unroll
    for (int o = 16; o; o >>= 1) {
        s  += __shfl_xor_sync(0xffffffffu, s, o);
        s2 += __shfl_xor_sync(0xffffffffu, s2, o);
    }
    if ((t & 31) == 0) { sh[t >> 5] = s; sh[8 + (t >> 5)] = s2; }
    __syncthreads();
    float ts = 0.f, ts2 = 0.f;
    #pragma unroll
    for (int i = 0; i < 8; i++) { ts += sh[i]; ts2 += sh[8 + i]; }
    float mu = ts * (1.f / HID);
    float var = ts2 * (1.f / HID) - mu * mu;
    float r = rsqrtf(var + 1e-6f);
    for (int j = t; j < HID; j += 256) {
        float v = (xr[j] - mu) * r;
        float xm = (1.f + g_m[HID + j]) * v + g_m[j];
        g_xmod[(size_t)l * HID + j] = xm;
        g_xmod2[(size_t)l * HID + j] = __float2half(xm);
    }
}

__global__ __launch_bounds__(256) void lora_down(
    const float* __restrict__ X, int ldx, const float* __restrict__ D,
    float* __restrict__ Y, int ldy, int K)
{
    __shared__ float xs[64][64];
    __shared__ float ds[64][32];
    int t = threadIdx.x;
    int m0 = blockIdx.x * 64;
    int tx = t & 31, ty = t >> 5;
    int xrow = t >> 2, xf4 = t & 3;
    int drow = t >> 3, df4 = t & 7;
    float acc[8] = {};

    for (int k0 = 0; k0 < K; k0 += 64) {
        #pragma unroll
        for (int j = 0; j < 4; j++) {
            int kk = (xf4 + 4 * j) * 4;
            float4 vx = *(const float4*)(X + (size_t)(m0 + xrow) * ldx + k0 + kk);
            xs[kk][xrow] = vx.x; xs[kk + 1][xrow] = vx.y;
            xs[kk + 2][xrow] = vx.z; xs[kk + 3][xrow] = vx.w;
        }
        #pragma unroll
        for (int j = 0; j < 2; j++) {
            int kk = (df4 + 8 * j) * 4;
            float4 vd = *(const float4*)(D + (size_t)drow * K + k0 + kk);
            ds[kk][drow] = vd.x; ds[kk + 1][drow] = vd.y;
            ds[kk + 2][drow] = vd.z; ds[kk + 3][drow] = vd.w;
        }
        __syncthreads();
        #pragma unroll
        for (int kk = 0; kk < 64; kk++) {
            float dv = ds[kk][tx];
            #pragma unroll
            for (int i = 0; i < 8; i++) acc[i] += xs[kk][ty * 8 + i] * dv;
        }
        __syncthreads();
    }
    #pragma unroll
    for (int i = 0; i < 8; i++)
        Y[(size_t)(m0 + ty * 8 + i) * ldy + tx] = acc[i];
}

__global__ __launch_bounds__(128) void qkv_finalize(
    const float* __restrict__ upq, const float* __restrict__ upk,
    const float* __restrict__ upv, const float* __restrict__ q_scale,
    const float* __restrict__ k_scale, const float* __restrict__ pe)
{
    int head = blockIdx.x, l = blockIdx.y, d = threadIdx.x;
    int col = head * HD + d;

    __shared__ float yq[32], yk[32], yv[32];
    __shared__ float sq[128], sk[128];
    __shared__ float wq[4], wk[4];

    if (d < 32)       yq[d]      = g_y1[(size_t)l * 32 + d];
    else if (d < 64)  yk[d - 32] = g_y1[(size_t)(L + l) * 32 + (d - 32)];
    else if (d < 96)  yv[d - 64] = g_y1[(size_t)(2 * L + l) * 32 + (d - 64)];
    __syncthreads();

    size_t hb = (size_t)l * H1;
    float qv = g_h[hb + col];
    float kv = g_h[hb + HID + col];
    float vv = g_h[hb + 2 * HID + col];

    {
        const float4* u = (const float4*)(upq + (size_t)col * 32);
        float a = 0.f;
        #pragma unroll
        for (int r = 0; r < 8; r++) {
            float4 t4 = u[r];
            a += t4.x * yq[4 * r] + t4.y * yq[4 * r + 1] + t4.z * yq[4 * r + 2] + t4.w * yq[4 * r + 3];
        }
        qv += a;
    }
    {
        const float4* u = (const float4*)(upk + (size_t)col * 32);
        float a = 0.f;
        #pragma unroll
        for (int r = 0; r < 8; r++) {
            float4 t4 = u[r];
            a += t4.x * yk[4 * r] + t4.y * yk[4 * r + 1] + t4.z * yk[4 * r + 2] + t4.w * yk[4 * r + 3];
        }
        kv += a;
    }
    {
        const float4* u = (const float4*)(upv + (size_t)col * 32);
        float a = 0.f;
        #pragma unroll
        for (int r = 0; r < 8; r++) {
            float4 t4 = u[r];
            a += t4.x * yv[4 * r] + t4.y * yv[4 * r + 1] + t4.z * yv[4 * r + 2] + t4.w * yv[4 * r + 3];
        }
        vv += a;
    }

    sq[d] = qv; sk[d] = kv;
    float aq = qv * qv, ak = kv * kv;
    #pragma unroll
    for (int o = 16; o; o >>= 1) {
        aq += __shfl_xor_sync(0xffffffffu, aq, o);
        ak += __shfl_xor_sync(0xffffffffu, ak, o);
    }
    if ((d & 31) == 0) { wq[d >> 5] = aq; wk[d >> 5] = ak; }
    __syncthreads();

    float rq = rsqrtf((wq[0] + wq[1] + wq[2] + wq[3]) * (1.f / HD) + 1e-6f);
    float rk = rsqrtf((wk[0] + wk[1] + wk[2] + wk[3]) * (1.f / HD) + 1e-6f);

    int e = d & ~1, o_ = d | 1;
    float q0 = sq[e]  * rq * q_scale[e];
    float q1 = sq[o_] * rq * q_scale[o_];
    float k0 = sk[e]  * rk * k_scale[e];
    float k1 = sk[o_] * rk * k_scale[o_];

    const float* p = pe + ((size_t)l * 64 + (d >> 1)) * 4;
    float qo = (d & 1) ? (p[2] * q0 + p[3] * q1) : (p[0] * q0 + p[1] * q1);
    float ko = (d & 1) ? (p[2] * k0 + p[3] * k1) : (p[0] * k0 + p[1] * k1);

    size_t qb = ((size_t)head * L + l) * HD + d;
    g_q2[qb] = __float2half(qo);
    g_k2[qb] = __float2half(ko);
    g_v2[((size_t)head * HD + d) * L + l] = __float2half(vv);
}

// softmax: fp32 scores -> fp16 probs
__global__ __launch_bounds__(256) void softmax_k() {
    const float* p = g_S + (size_t)blockIdx.x * L;
    __half* o = g_S2 + (size_t)blockIdx.x * L;
    int t = threadIdx.x;
    __shared__ float buf[L];
    __shared__ float sh[8];

    float mx = -1e30f;
    for (int j = t; j < L; j += 256) { float v = p[j]; buf[j] = v; mx = fmaxf(mx, v); }
    #pragma unroll
    for (int s = 16; s; s >>= 1) mx = fmaxf(mx, __shfl_xor_sync(0xffffffffu, mx, s));
    if ((t & 31) == 0) sh[t >> 5] = mx;
    __syncthreads();
    float m2 = sh[0];
    #pragma unroll
    for (int i = 1; i < 8; i++) m2 = fmaxf(m2, sh[i]);

    float sum = 0.f;
    for (int j = t; j < L; j += 256) {
        float e = __expf(buf[j] - m2);
        buf[j] = e;
        sum += e;
    }
    #pragma unroll
    for (int s = 16; s; s >>= 1) sum += __shfl_xor_sync(0xffffffffu, sum, s);
    if ((t & 31) == 0) sh[t >> 5] = sum;
    __syncthreads();
    float s2 = 0.f;
    #pragma unroll
    for (int i = 0; i < 8; i++) s2 += sh[i];
    float inv = 1.f / s2;
    for (int j = t; j < L; j += 256) o[j] = __float2half(buf[j] * inv);
}

__global__ void gelu_k() {
    size_t i = (size_t)blockIdx.x * 256 + threadIdx.x;
    size_t l = i / MLPD, j = i % MLPD;
    float xv = g_h[l * H1 + 3 * HID + j];
    float g = 0.5f * xv * (1.f + tanhf(0.7978845608028654f * (xv + 0.044715f * xv * xv * xv)));
    g_cat[l * CATD + HID + j] = g;
}

__global__ __launch_bounds__(256) void final_k(const float* __restrict__ x,
                                               const float* __restrict__ pu,
                                               float* __restrict__ out)
{
    int l = blockIdx.y;
    int c = blockIdx.x * 256 + threadIdx.x;
    __shared__ float sp[64];
    if (threadIdx.x < 64) sp[threadIdx.x] = g_pl[(size_t)l * 64 + threadIdx.x];
    __syncthreads();

    const float4* ur = (const float4*)(pu + (size_t)c * 64);
    float a = 0.f;
    #pragma unroll
    for (int r = 0; r < 16; r++) {
        float4 u = ur[r];
        a += u.x * sp[4 * r] + u.y * sp[4 * r + 1] + u.z * sp[4 * r + 2] + u.w * sp[4 * r + 3];
    }
    size_t idx = (size_t)l * HID + c;
    float o = g_o[idx] + a;
    out[idx] = x[idx] + g_m[2 * HID + c] * o;
}

// ================= launch =================
extern "C" void kernel_launch(void* const* d_in, const int* in_sizes, int n_in,
                              void* d_out, int out_size)
{
    const float* x   = (const float*)d_in[0];
    const float* vec = (const float*)d_in[1];
    const float* pe  = (const float*)d_in[2];
    const float* mw  = (const float*)d_in[3];
    const float* mb  = (const float*)d_in[4];
    const float* w1  = (const float*)d_in[5];
    const float* b1  = (const float*)d_in[6];
    const float* w2  = (const float*)d_in[7];
    const float* b2  = (const float*)d_in[8];
    const float* qs  = (const float*)d_in[9];
    const float* ks  = (const float*)d_in[10];
    const float* lqd = (const float*)d_in[11];
    const float* lqu = (const float*)d_in[12];
    const float* lkd = (const float*)d_in[13];
    const float* lku = (const float*)d_in[14];
    const float* lvd = (const float*)d_in[15];
    const float* lvu = (const float*)d_in[16];
    const float* pd  = (const float*)d_in[17];
    const float* pu  = (const float*)d_in[18];
    float* out = (float*)d_out;

    float *xmod, *h, *y1, *S, *cat, *ob, *pl;
    __half *xmod2, *w12, *w22, *cat2, *q2, *k2, *v2, *S2;
    cudaGetSymbolAddress((void**)&xmod,  g_xmod);
    cudaGetSymbolAddress((void**)&h,     g_h);
    cudaGetSymbolAddress((void**)&y1,    g_y1);
    cudaGetSymbolAddress((void**)&S,     g_S);
    cudaGetSymbolAddress((void**)&cat,   g_cat);
    cudaGetSymbolAddress((void**)&ob,    g_o);
    cudaGetSymbolAddress((void**)&pl,    g_pl);
    cudaGetSymbolAddress((void**)&xmod2, g_xmod2);
    cudaGetSymbolAddress((void**)&w12,   g_w12);
    cudaGetSymbolAddress((void**)&w22,   g_w22);
    cudaGetSymbolAddress((void**)&cat2,  g_cat2);
    cudaGetSymbolAddress((void**)&q2,    g_q2);
    cudaGetSymbolAddress((void**)&k2,    g_k2);
    cudaGetSymbolAddress((void**)&v2,    g_v2);
    cudaGetSymbolAddress((void**)&S2,    g_S2);

    const int SM256 = 3 * (128 + 256) * 128;   // 147456
    const int SM128 = 3 * (128 + 128) * 128;   // 98304
    cudaFuncSetAttribute(gemm_hf<256, true>,  cudaFuncAttributeMaxDynamicSharedMemorySize, SM256);
    cudaFuncSetAttribute(gemm_hf<256, false>, cudaFuncAttributeMaxDynamicSharedMemorySize, SM256);
    cudaFuncSetAttribute(gemm_hf<128, false>, cudaFuncAttributeMaxDynamicSharedMemorySize, SM128);

    // 1) modulation vector
    silu_k<<<12, 256>>>(vec);
    mod_gemv<<<(3 * HID) / 8, 256>>>(mw, mb);

    // 2) modulated layernorm (writes fp32 + fp16 x_mod)
    ln_mod_k<<<L, 256>>>(x);

    // 3) convert w1 to fp16
    conv_half<<<(int)(((size_t)H1 * HID / 8 + 255) / 256), 256>>>(w1, w12, (size_t)H1 * HID / 8);

    // 4) h = x_mod @ w1^T + b1
    gemm_hf<256, true><<<dim3(L / 128, H1 / 256, 1), 256, SM256>>>(
        xmod2, w12, h, b1, HID, HID, HID, H1, 0LL, 0LL, 0LL, 1.f);

    // 5) lora downs (fp32)
    lora_down<<<L / 64, 256>>>(xmod, HID, lqd, y1,                      32, HID);
    lora_down<<<L / 64, 256>>>(xmod, HID, lkd, y1 + (size_t)L * 32,     32, HID);
    lora_down<<<L / 64, 256>>>(xmod, HID, lvd, y1 + (size_t)2 * L * 32, 32, HID);

    // 6) assemble q,k,v -> fp16
    qkv_finalize<<<dim3(HEADS, L), 128>>>(lqu, lku, lvu, qs, ks, pe);

    // 7) scores = q @ k^T / sqrt(HD)
    gemm_hf<256, false><<<dim3(L / 128, L / 256, HEADS), 256, SM256>>>(
        q2, k2, S, nullptr, HD, HD, HD, L,
        (long long)L * HD, (long long)L * HD, (long long)L * L,
        0.08838834764831845f);

    // 8) softmax -> fp16 probs
    softmax_k<<<HEADS * L, 256>>>();

    // 9) attn_out = P @ V -> cat left half
    gemm_hf<128, false><<<dim3(L / 128, 1, HEADS), 256, SM128>>>(
        S2, v2, cat, nullptr, L, L, L, CATD,
        (long long)L * L, (long long)HD * L, 128LL, 1.f);

    // 10) gelu(mlp) -> cat right half
    gelu_k<<<(int)(((size_t)L * MLPD) / 256), 256>>>();

    // 11) convert cat and w2 to fp16
    conv_half<<<(int)(((size_t)L * CATD / 8 + 255) / 256), 256>>>(cat, cat2, (size_t)L * CATD / 8);
    conv_half<<<(int)(((size_t)HID * CATD / 8 + 255) / 256), 256>>>(w2, w22, (size_t)HID * CATD / 8);

    // 12) out_lin = cat @ w2^T + b2
    gemm_hf<256, true><<<dim3(L / 128, HID / 256, 1), 256, SM256>>>(
        cat2, w22, ob, b2, CATD, CATD, CATD, HID, 0LL, 0LL, 0LL, 1.f);

    // 13) proj lora down (rank 64 as two rank-32 halves, fp32)
    lora_down<<<L / 64, 256>>>(cat, CATD, pd,                     pl,      64, CATD);
    lora_down<<<L / 64, 256>>>(cat, CATD, pd + (size_t)32 * CATD, pl + 32, 64, CATD);

    // 14) final residual
    final_k<<<dim3(HID / 256, L), 256>>>(x, pu, out);
}

// round 5
// speedup vs baseline: 3.6639x; 1.0228x over previous
#include <cuda_runtime.h>
#include <cuda_fp16.h>
#include <math.h>
#include <stdint.h>

#define L 2048
#define HID 3072
#define HEADS 24
#define HD 128
#define MLPD 12288
#define H1 21504    // 3*HID + MLP
#define CATD 15360  // HID + MLP

// ---------------- scratch ----------------
__device__ float g_sv[HID];
__device__ float g_m[3 * HID];
__device__ float g_h[(size_t)L * 3 * HID];        // qkv part of h (fp32)
__device__ float g_y1[3 * (size_t)L * 32];
__device__ float g_o[(size_t)L * HID];
__device__ float g_pl[(size_t)L * 64];

__device__ __half g_xmod2[(size_t)L * HID];
__device__ __half g_w12[(size_t)H1 * HID];
__device__ __half g_w22[(size_t)HID * CATD];
__device__ __half g_cat2[(size_t)L * CATD];       // [attn | gelu(mlp)] fp16
__device__ __half g_q2[(size_t)HEADS * L * HD];
__device__ __half g_k2[(size_t)HEADS * L * HD];
__device__ __half g_v2[(size_t)HEADS * HD * L];   // [h][d][l]

// ================= helpers =================
__device__ __forceinline__ uint32_t smem_u32(const void* p) {
    uint32_t a;
    asm("{ .reg .u64 t; cvta.to.shared.u64 t, %1; cvt.u32.u64 %0, t; }" : "=r"(a) : "l"(p));
    return a;
}
__device__ __forceinline__ void cpasync16(uint32_t dst, const void* src) {
    asm volatile("cp.async.cg.shared.global [%0], [%1], 16;" :: "r"(dst), "l"(src) : "memory");
}
__device__ __forceinline__ void ldsm4(uint32_t& r0, uint32_t& r1, uint32_t& r2, uint32_t& r3,
                                      uint32_t addr) {
    asm volatile("ldmatrix.sync.aligned.m8n8.x4.shared.b16 {%0,%1,%2,%3}, [%4];"
                 : "=r"(r0), "=r"(r1), "=r"(r2), "=r"(r3) : "r"(addr));
}
__device__ __forceinline__ void mma16816(float* d, const uint32_t* a, const uint32_t* b) {
    asm volatile(
        "mma.sync.aligned.m16n8k16.row.col.f32.f16.f16.f32 "
        "{%0,%1,%2,%3}, {%4,%5,%6,%7}, {%8,%9}, {%0,%1,%2,%3};"
        : "+f"(d[0]), "+f"(d[1]), "+f"(d[2]), "+f"(d[3])
        : "r"(a[0]), "r"(a[1]), "r"(a[2]), "r"(a[3]), "r"(b[0]), "r"(b[1]));
}
__device__ __forceinline__ uint32_t packh2(float a, float b) {
    __half2 h = __floats2half2_rn(a, b);
    return *(uint32_t*)&h;
}
__device__ __forceinline__ float gelu1(float x) {
    return 0.5f * x * (1.f + tanhf(0.7978845608028654f * (x + 0.044715f * x * x * x)));
}
// swizzled address for a tile stored as rows of 128B (cols = 64 halves)
__device__ __forceinline__ uint32_t swz128(uint32_t base, int r, int q) {
    return base + (uint32_t)r * 128u + ((uint32_t)(q ^ (r & 7)) << 4);
}
// tile with 256B logical rows stored as 2x 128B smem rows
__device__ __forceinline__ uint32_t swz256(uint32_t base, int r, int q8) {
    int sr = r * 2 + (q8 >> 3);
    int q = q8 & 7;
    return base + (uint32_t)sr * 128u + ((uint32_t)(q ^ (sr & 7)) << 4);
}

// ================= 512-thread fp16 NT GEMM =================
// MODE 0: C = A@B^T + bias -> C fp32 (ldc)
// MODE 1: h|gelu split: n0<9216 -> g_h fp32 (ldc=3*HID); else gelu -> catp fp16
template <int MODE>
__global__ __launch_bounds__(512, 1) void gemm512(
    const __half* __restrict__ A2, const __half* __restrict__ B2,
    float* __restrict__ C, const float* __restrict__ bias,
    __half* __restrict__ catp, int K, int lda, int ldb, int ldc)
{
    constexpr uint32_t ABYTES = 128u * 128u;
    constexpr uint32_t BBYTES = 256u * 128u;
    constexpr uint32_t STAGE = ABYTES + BBYTES;   // 48KB

    extern __shared__ char smraw[];
    uint32_t s0 = smem_u32(smraw);

    const int t = threadIdx.x, w = t >> 5, lane = t & 31;
    const int wm = w & 3, wn = w >> 2;
    const int m0 = blockIdx.x * 128, n0 = blockIdx.y * 256;
    const int nc = K >> 6;

    auto issue = [&](int c, int stg) {
        uint32_t ab = s0 + (uint32_t)stg * STAGE;
        const __half* Ap = A2 + (size_t)m0 * lda + c * 64;
        #pragma unroll
        for (int i = 0; i < 2; i++) {
            int f = t + i * 512, r = f >> 3, q = f & 7;
            cpasync16(swz128(ab, r, q), Ap + (size_t)r * lda + q * 8);
        }
        uint32_t bb = ab + ABYTES;
        const __half* Bp = B2 + (size_t)n0 * ldb + c * 64;
        #pragma unroll
        for (int i = 0; i < 4; i++) {
            int f = t + i * 512, r = f >> 3, q = f & 7;
            cpasync16(swz128(bb, r, q), Bp + (size_t)r * ldb + q * 8);
        }
        asm volatile("cp.async.commit_group;" ::: "memory");
    };

    float acc[2][8][4] = {};

    issue(0, 0);
    issue(1, 1);

    for (int c = 0; c < nc; c++) {
        if (c + 1 < nc) asm volatile("cp.async.wait_group 1;" ::: "memory");
        else            asm volatile("cp.async.wait_group 0;" ::: "memory");
        __syncthreads();
        if (c + 2 < nc) issue(c + 2, (c + 2) % 3);

        uint32_t ab = s0 + (uint32_t)(c % 3) * STAGE;
        uint32_t bb = ab + ABYTES;

        #pragma unroll
        for (int s = 0; s < 4; s++) {
            uint32_t Af[2][4];
            #pragma unroll
            for (int mt = 0; mt < 2; mt++) {
                int r = wm * 32 + mt * 16 + (lane & 15);
                int q = s * 2 + (lane >> 4);
                ldsm4(Af[mt][0], Af[mt][1], Af[mt][2], Af[mt][3], swz128(ab, r, q));
            }
            uint32_t Bf[8][2];
            #pragma unroll
            for (int np = 0; np < 4; np++) {
                int r = wn * 64 + np * 16 + ((lane >> 4) << 3) + (lane & 7);
                int q = s * 2 + ((lane >> 3) & 1);
                ldsm4(Bf[2 * np][0], Bf[2 * np][1], Bf[2 * np + 1][0], Bf[2 * np + 1][1],
                      swz128(bb, r, q));
            }
            #pragma unroll
            for (int mt = 0; mt < 2; mt++)
                #pragma unroll
                for (int nt = 0; nt < 8; nt++)
                    mma16816(acc[mt][nt], Af[mt], Bf[nt]);
        }
    }

    // epilogue
    #pragma unroll
    for (int mt = 0; mt < 2; mt++) {
        int row = m0 + wm * 32 + mt * 16 + (lane >> 2);
        #pragma unroll
        for (int nt = 0; nt < 8; nt++) {
            int col = n0 + wn * 64 + nt * 8 + (lane & 3) * 2;
            float b0 = bias[col], b1v = bias[col + 1];
            float v00 = acc[mt][nt][0] + b0, v01 = acc[mt][nt][1] + b1v;
            float v10 = acc[mt][nt][2] + b0, v11 = acc[mt][nt][3] + b1v;
            if (MODE == 1 && n0 >= 3 * HID) {
                size_t cc = (size_t)col - 6144;   // col - 3*HID + HID
                *(__half2*)(catp + (size_t)row * CATD + cc) =
                    __floats2half2_rn(gelu1(v00), gelu1(v01));
                *(__half2*)(catp + (size_t)(row + 8) * CATD + cc) =
                    __floats2half2_rn(gelu1(v10), gelu1(v11));
            } else {
                *(float2*)(C + (size_t)row * ldc + col)       = make_float2(v00, v01);
                *(float2*)(C + (size_t)(row + 8) * ldc + col) = make_float2(v10, v11);
            }
        }
    }
}

// ================= flash attention =================
// grid (16, 24), 256 threads. Q,K: [h][l][d]; V: [h][d][l]; out -> cat2 cols head*128..+128
__global__ __launch_bounds__(256, 1) void flash_k(
    const __half* __restrict__ Qg, const __half* __restrict__ Kg,
    const __half* __restrict__ Vg, __half* __restrict__ catp)
{
    extern __shared__ char smraw[];
    uint32_t s0 = smem_u32(smraw);
    const uint32_t sQ = s0;
    const uint32_t sK[2] = {s0 + 32768u, s0 + 98304u};
    const uint32_t sV[2] = {s0 + 65536u, s0 + 131072u};

    const int t = threadIdx.x, w = t >> 5, lane = t & 31;
    const int qt = blockIdx.x, head = blockIdx.y;

    const __half* Qp = Qg + ((size_t)head * L + qt * 128) * HD;
    const __half* Kp = Kg + (size_t)head * L * HD;
    const __half* Vp = Vg + (size_t)head * HD * L;

    auto ld_tile = [&](uint32_t dst, const __half* src, int ld) {
        #pragma unroll
        for (int i = 0; i < 8; i++) {
            int f = t + i * 256, r = f >> 4, q8 = f & 15;
            cpasync16(swz256(dst, r, q8), src + (size_t)r * ld + q8 * 8);
        }
    };

    ld_tile(sQ, Qp, HD);
    ld_tile(sK[0], Kp, HD);
    ld_tile(sV[0], Vp, L);
    asm volatile("cp.async.commit_group;" ::: "memory");

    const float CSC = 0.08838834764831845f * 1.4426950408889634f;
    float m_[2] = {-1e30f, -1e30f}, l_[2] = {0.f, 0.f};
    float oacc[16][4] = {};

    for (int kt = 0; kt < 16; kt++) {
        asm volatile("cp.async.wait_group 0;" ::: "memory");
        __syncthreads();
        int buf = kt & 1;
        if (kt + 1 < 16) {
            ld_tile(sK[buf ^ 1], Kp + (size_t)(kt + 1) * 128 * HD, HD);
            ld_tile(sV[buf ^ 1], Vp + (kt + 1) * 128, L);
            asm volatile("cp.async.commit_group;" ::: "memory");
        }

        // S = Q @ K^T (warp: rows w*16..+15, all 128 keys)
        float sacc[16][4] = {};
        #pragma unroll
        for (int ks = 0; ks < 8; ks++) {
            uint32_t Af[4];
            {
                int r = w * 16 + (lane & 15);
                int q8 = ks * 2 + (lane >> 4);
                ldsm4(Af[0], Af[1], Af[2], Af[3], swz256(sQ, r, q8));
            }
            uint32_t Bf[16][2];
            #pragma unroll
            for (int np = 0; np < 8; np++) {
                int r = np * 16 + ((lane >> 4) << 3) + (lane & 7);
                int q8 = ks * 2 + ((lane >> 3) & 1);
                ldsm4(Bf[2 * np][0], Bf[2 * np][1], Bf[2 * np + 1][0], Bf[2 * np + 1][1],
                      swz256(sK[buf], r, q8));
            }
            #pragma unroll
            for (int nt = 0; nt < 16; nt++) mma16816(sacc[nt], Af, Bf[nt]);
        }

        // online softmax (rows: lane>>2 for h=0, +8 for h=1)
        #pragma unroll
        for (int h = 0; h < 2; h++) {
            float tm = -1e30f;
            #pragma unroll
            for (int nt = 0; nt < 16; nt++)
                tm = fmaxf(tm, fmaxf(sacc[nt][2 * h], sacc[nt][2 * h + 1]));
            tm *= CSC;
            tm = fmaxf(tm, __shfl_xor_sync(0xffffffffu, tm, 1));
            tm = fmaxf(tm, __shfl_xor_sync(0xffffffffu, tm, 2));
            float mn = fmaxf(m_[h], tm);
            float alpha = exp2f(m_[h] - mn);
            float rs = 0.f;
            #pragma unroll
            for (int nt = 0; nt < 16; nt++) {
                float p0 = exp2f(sacc[nt][2 * h] * CSC - mn);
                float p1 = exp2f(sacc[nt][2 * h + 1] * CSC - mn);
                sacc[nt][2 * h] = p0; sacc[nt][2 * h + 1] = p1;
                rs += p0 + p1;
            }
            rs += __shfl_xor_sync(0xffffffffu, rs, 1);
            rs += __shfl_xor_sync(0xffffffffu, rs, 2);
            l_[h] = l_[h] * alpha + rs;
            m_[h] = mn;
            #pragma unroll
            for (int nt = 0; nt < 16; nt++) { oacc[nt][2 * h] *= alpha; oacc[nt][2 * h + 1] *= alpha; }
        }

        // O += P @ V  (P from sacc regs; B from V^T tile: rows=d, cols=key)
        #pragma unroll
        for (int kk = 0; kk < 8; kk++) {
            uint32_t pf[4];
            pf[0] = packh2(sacc[2 * kk][0], sacc[2 * kk][1]);
            pf[1] = packh2(sacc[2 * kk][2], sacc[2 * kk][3]);
            pf[2] = packh2(sacc[2 * kk + 1][0], sacc[2 * kk + 1][1]);
            pf[3] = packh2(sacc[2 * kk + 1][2], sacc[2 * kk + 1][3]);
            uint32_t Bv[16][2];
            #pragma unroll
            for (int np = 0; np < 8; np++) {
                int r = np * 16 + ((lane >> 4) << 3) + (lane & 7);
                int q8 = kk * 2 + ((lane >> 3) & 1);
                ldsm4(Bv[2 * np][0], Bv[2 * np][1], Bv[2 * np + 1][0], Bv[2 * np + 1][1],
                      swz256(sV[buf], r, q8));
            }
            #pragma unroll
            for (int nt = 0; nt < 16; nt++) mma16816(oacc[nt], pf, Bv[nt]);
        }
    }

    float inv0 = 1.f / l_[0], inv1 = 1.f / l_[1];
    int row0 = qt * 128 + w * 16 + (lane >> 2);
    #pragma unroll
    for (int nt = 0; nt < 16; nt++) {
        int col = head * 128 + nt * 8 + (lane & 3) * 2;
        *(__half2*)(catp + (size_t)row0 * CATD + col) =
            __floats2half2_rn(oacc[nt][0] * inv0, oacc[nt][1] * inv0);
        *(__half2*)(catp + (size_t)(row0 + 8) * CATD + col) =
            __floats2half2_rn(oacc[nt][2] * inv1, oacc[nt][3] * inv1);
    }
}

// ================= fp32 -> fp16 streaming convert =================
__global__ void conv_half(const float* __restrict__ src, __half* __restrict__ dst,
                          long long n8) {
    long long i = (long long)blockIdx.x * 256 + threadIdx.x;
    if (i >= n8) return;
    const float4* s = (const float4*)(src + i * 8);
    float4 a = s[0], b = s[1];
    __half2 h0 = __floats2half2_rn(a.x, a.y);
    __half2 h1 = __floats2half2_rn(a.z, a.w);
    __half2 h2 = __floats2half2_rn(b.x, b.y);
    __half2 h3 = __floats2half2_rn(b.z, b.w);
    uint4 o;
    o.x = *(uint32_t*)&h0; o.y = *(uint32_t*)&h1;
    o.z = *(uint32_t*)&h2; o.w = *(uint32_t*)&h3;
    ((uint4*)dst)[i] = o;
}

// ================= small kernels =================
__global__ void silu_k(const float* __restrict__ vec) {
    int i = blockIdx.x * 256 + threadIdx.x;
    if (i < HID) { float v = vec[i]; g_sv[i] = v / (1.f + expf(-v)); }
}

__global__ __launch_bounds__(256) void mod_gemv(const float* __restrict__ W,
                                                const float* __restrict__ b) {
    int o = blockIdx.x * 8 + (threadIdx.x >> 5);
    int lane = threadIdx.x & 31;
    const float* w = W + (size_t)o * HID;
    float acc = 0.f;
    for (int k = lane; k < HID; k += 32) acc += g_sv[k] * w[k];
    #pragma unroll
    for (int s = 16; s; s >>= 1) acc += __shfl_xor_sync(0xffffffffu, acc, s);
    if (lane == 0) g_m[o] = acc + b[o];
}

__global__ __launch_bounds__(256) void ln_mod_k(const float* __restrict__ x) {
    int l = blockIdx.x, t = threadIdx.x;
    const float* xr = x + (size_t)l * HID;
    float s = 0.f, s2 = 0.f;
    for (int j = t; j < HID; j += 256) { float v = xr[j]; s += v; s2 += v * v; }
    __shared__ float sh[16];
    #pragma unroll
    for (int o = 16; o; o >>= 1) {
        s  += __shfl_xor_sync(0xffffffffu, s, o);
        s2 += __shfl_xor_sync(0xffffffffu, s2, o);
    }
    if ((t & 31) == 0) { sh[t >> 5] = s; sh[8 + (t >> 5)] = s2; }
    __syncthreads();
    float ts = 0.f, ts2 = 0.f;
    #pragma unroll
    for (int i = 0; i < 8; i++) { ts += sh[i]; ts2 += sh[8 + i]; }
    float mu = ts * (1.f / HID);
    float var = ts2 * (1.f / HID) - mu * mu;
    float r = rsqrtf(var + 1e-6f);
    for (int j = t; j < HID; j += 256) {
        float v = (xr[j] - mu) * r;
        float xm = (1.f + g_m[HID + j]) * v + g_m[j];
        g_xmod2[(size_t)l * HID + j] = __float2half(xm);
    }
}

// lora down with fp16 X: Y(64-rows, 32 cols) = X @ D^T
__global__ __launch_bounds__(256) void lora_down_h(
    const __half* __restrict__ X, int ldx, const float* __restrict__ D,
    float* __restrict__ Y, int ldy, int K)
{
    __shared__ float xs[64][64];
    __shared__ float ds[64][32];
    int t = threadIdx.x;
    int m0 = blockIdx.x * 64;
    int tx = t & 31, ty = t >> 5;
    int drow = t >> 3, df4 = t & 7;
    float acc[8] = {};

    for (int k0 = 0; k0 < K; k0 += 64) {
        #pragma unroll
        for (int j = 0; j < 4; j++) {
            int slot = t + j * 256;
            int row = slot >> 4, c = (slot & 15) * 4;
            const __half* Xr = X + (size_t)(m0 + row) * ldx + k0 + c;
            __half2 ab = *(const __half2*)(Xr);
            __half2 cd = *(const __half2*)(Xr + 2);
            float2 f0 = __half22float2(ab), f1 = __half22float2(cd);
            xs[c][row] = f0.x; xs[c + 1][row] = f0.y;
            xs[c + 2][row] = f1.x; xs[c + 3][row] = f1.y;
        }
        #pragma unroll
        for (int j = 0; j < 2; j++) {
            int kk = (df4 + 8 * j) * 4;
            float4 vd = *(const float4*)(D + (size_t)drow * K + k0 + kk);
            ds[kk][drow] = vd.x; ds[kk + 1][drow] = vd.y;
            ds[kk + 2][drow] = vd.z; ds[kk + 3][drow] = vd.w;
        }
        __syncthreads();
        #pragma unroll
        for (int kk = 0; kk < 64; kk++) {
            float dv = ds[kk][tx];
            #pragma unroll
            for (int i = 0; i < 8; i++) acc[i] += xs[kk][ty * 8 + i] * dv;
        }
        __syncthreads();
    }
    #pragma unroll
    for (int i = 0; i < 8; i++)
        Y[(size_t)(m0 + ty * 8 + i) * ldy + tx] = acc[i];
}

__global__ __launch_bounds__(128) void qkv_finalize(
    const float* __restrict__ upq, const float* __restrict__ upk,
    const float* __restrict__ upv, const float* __restrict__ q_scale,
    const float* __restrict__ k_scale, const float* __restrict__ pe)
{
    int head = blockIdx.x, l = blockIdx.y, d = threadIdx.x;
    int col = head * HD + d;

    __shared__ float yq[32], yk[32], yv[32];
    __shared__ float sq[128], sk[128];
    __shared__ float wq[4], wk[4];

    if (d < 32)       yq[d]      = g_y1[(size_t)l * 32 + d];
    else if (d < 64)  yk[d - 32] = g_y1[(size_t)(L + l) * 32 + (d - 32)];
    else if (d < 96)  yv[d - 64] = g_y1[(size_t)(2 * L + l) * 32 + (d - 64)];
    __syncthreads();

    size_t hb = (size_t)l * (3 * HID);
    float qv = g_h[hb + col];
    float kv = g_h[hb + HID + col];
    float vv = g_h[hb + 2 * HID + col];

    {
        const float4* u = (const float4*)(upq + (size_t)col * 32);
        float a = 0.f;
        #pragma unroll
        for (int r = 0; r < 8; r++) {
            float4 t4 = u[r];
            a += t4.x * yq[4 * r] + t4.y * yq[4 * r + 1] + t4.z * yq[4 * r + 2] + t4.w * yq[4 * r + 3];
        }
        qv += a;
    }
    {
        const float4* u = (const float4*)(upk + (size_t)col * 32);
        float a = 0.f;
        #pragma unroll
        for (int r = 0; r < 8; r++) {
            float4 t4 = u[r];
            a += t4.x * yk[4 * r] + t4.y * yk[4 * r + 1] + t4.z * yk[4 * r + 2] + t4.w * yk[4 * r + 3];
        }
        kv += a;
    }
    {
        const float4* u = (const float4*)(upv + (size_t)col * 32);
        float a = 0.f;
        #pragma unroll
        for (int r = 0; r < 8; r++) {
            float4 t4 = u[r];
            a += t4.x * yv[4 * r] + t4.y * yv[4 * r + 1] + t4.z * yv[4 * r + 2] + t4.w * yv[4 * r + 3];
        }
        vv += a;
    }

    sq[d] = qv; sk[d] = kv;
    float aq = qv * qv, ak = kv * kv;
    #pragma unroll
    for (int o = 16; o; o >>= 1) {
        aq += __shfl_xor_sync(0xffffffffu, aq, o);
        ak += __shfl_xor_sync(0xffffffffu, ak, o);
    }
    if ((d & 31) == 0) { wq[d >> 5] = aq; wk[d >> 5] = ak; }
    __syncthreads();

    float rq = rsqrtf((wq[0] + wq[1] + wq[2] + wq[3]) * (1.f / HD) + 1e-6f);
    float rk = rsqrtf((wk[0] + wk[1] + wk[2] + wk[3]) * (1.f / HD) + 1e-6f);

    int e = d & ~1, o_ = d | 1;
    float q0 = sq[e]  * rq * q_scale[e];
    float q1 = sq[o_] * rq * q_scale[o_];
    float k0 = sk[e]  * rk * k_scale[e];
    float k1 = sk[o_] * rk * k_scale[o_];

    const float* p = pe + ((size_t)l * 64 + (d >> 1)) * 4;
    float qo = (d & 1) ? (p[2] * q0 + p[3] * q1) : (p[0] * q0 + p[1] * q1);
    float ko = (d & 1) ? (p[2] * k0 + p[3] * k1) : (p[0] * k0 + p[1] * k1);

    size_t qb = ((size_t)head * L + l) * HD + d;
    g_q2[qb] = __float2half(qo);
    g_k2[qb] = __float2half(ko);
    g_v2[((size_t)head * HD + d) * L + l] = __float2half(vv);
}

__global__ __launch_bounds__(256) void final_k(const float* __restrict__ x,
                                               const float* __restrict__ pu,
                                               float* __restrict__ out)
{
    int l = blockIdx.y;
    int c = blockIdx.x * 256 + threadIdx.x;
    __shared__ float sp[64];
    if (threadIdx.x < 64) sp[threadIdx.x] = g_pl[(size_t)l * 64 + threadIdx.x];
    __syncthreads();

    const float4* ur = (const float4*)(pu + (size_t)c * 64);
    float a = 0.f;
    #pragma unroll
    for (int r = 0; r < 16; r++) {
        float4 u = ur[r];
        a += u.x * sp[4 * r] + u.y * sp[4 * r + 1] + u.z * sp[4 * r + 2] + u.w * sp[4 * r + 3];
    }
    size_t idx = (size_t)l * HID + c;
    float o = g_o[idx] + a;
    out[idx] = x[idx] + g_m[2 * HID + c] * o;
}

// ================= launch =================
extern "C" void kernel_launch(void* const* d_in, const int* in_sizes, int n_in,
                              void* d_out, int out_size)
{
    const float* x   = (const float*)d_in[0];
    const float* vec = (const float*)d_in[1];
    const float* pe  = (const float*)d_in[2];
    const float* mw  = (const float*)d_in[3];
    const float* mb  = (const float*)d_in[4];
    const float* w1  = (const float*)d_in[5];
    const float* b1  = (const float*)d_in[6];
    const float* w2  = (const float*)d_in[7];
    const float* b2  = (const float*)d_in[8];
    const float* qs  = (const float*)d_in[9];
    const float* ks  = (const float*)d_in[10];
    const float* lqd = (const float*)d_in[11];
    const float* lqu = (const float*)d_in[12];
    const float* lkd = (const float*)d_in[13];
    const float* lku = (const float*)d_in[14];
    const float* lvd = (const float*)d_in[15];
    const float* lvu = (const float*)d_in[16];
    const float* pd  = (const float*)d_in[17];
    const float* pu  = (const float*)d_in[18];
    float* out = (float*)d_out;

    float *h, *y1, *ob, *pl;
    __half *xmod2, *w12, *w22, *cat2, *q2, *k2, *v2;
    cudaGetSymbolAddress((void**)&h,     g_h);
    cudaGetSymbolAddress((void**)&y1,    g_y1);
    cudaGetSymbolAddress((void**)&ob,    g_o);
    cudaGetSymbolAddress((void**)&pl,    g_pl);
    cudaGetSymbolAddress((void**)&xmod2, g_xmod2);
    cudaGetSymbolAddress((void**)&w12,   g_w12);
    cudaGetSymbolAddress((void**)&w22,   g_w22);
    cudaGetSymbolAddress((void**)&cat2,  g_cat2);
    cudaGetSymbolAddress((void**)&q2,    g_q2);
    cudaGetSymbolAddress((void**)&k2,    g_k2);
    cudaGetSymbolAddress((void**)&v2,    g_v2);

    const int SMG = 3 * 48 * 1024;       // 147456
    const int SMF = 5 * 32 * 1024;       // 163840
    cudaFuncSetAttribute(gemm512<1>, cudaFuncAttributeMaxDynamicSharedMemorySize, SMG);
    cudaFuncSetAttribute(gemm512<0>, cudaFuncAttributeMaxDynamicSharedMemorySize, SMG);
    cudaFuncSetAttribute(flash_k,    cudaFuncAttributeMaxDynamicSharedMemorySize, SMF);

    // 1) modulation vector
    silu_k<<<12, 256>>>(vec);
    mod_gemv<<<(3 * HID) / 8, 256>>>(mw, mb);

    // 2) modulated layernorm -> fp16 x_mod
    ln_mod_k<<<L, 256>>>(x);

    // 3) convert w1
    conv_half<<<(int)(((size_t)H1 * HID / 8 + 255) / 256), 256>>>(w1, w12, (size_t)H1 * HID / 8);

    // 4) gemm1: h(qkv fp32) + gelu(mlp)->cat2 fp16
    gemm512<1><<<dim3(L / 128, H1 / 256), 512, SMG>>>(
        xmod2, w12, h, b1, cat2, HID, HID, HID, 3 * HID);

    // 5) q/k/v lora downs (fp16 X)
    lora_down_h<<<L / 64, 256>>>(xmod2, HID, lqd, y1,                      32, HID);
    lora_down_h<<<L / 64, 256>>>(xmod2, HID, lkd, y1 + (size_t)L * 32,     32, HID);
    lora_down_h<<<L / 64, 256>>>(xmod2, HID, lvd, y1 + (size_t)2 * L * 32, 32, HID);

    // 6) assemble q,k,v -> fp16
    qkv_finalize<<<dim3(HEADS, L), 128>>>(lqu, lku, lvu, qs, ks, pe);

    // 7) fused attention -> cat2 left half
    flash_k<<<dim3(L / 128, HEADS), 256, SMF>>>(q2, k2, v2, cat2);

    // 8) convert w2
    conv_half<<<(int)(((size_t)HID * CATD / 8 + 255) / 256), 256>>>(w2, w22, (size_t)HID * CATD / 8);

    // 9) gemm2: o = cat @ w2^T + b2
    gemm512<0><<<dim3(L / 128, HID / 256), 512, SMG>>>(
        cat2, w22, ob, b2, nullptr, CATD, CATD, CATD, HID);

    // 10) proj lora down (rank 64 as two rank-32 halves), X = cat2 fp16
    lora_down_h<<<L / 64, 256>>>(cat2, CATD, pd,                     pl,      64, CATD);
    lora_down_h<<<L / 64, 256>>>(cat2, CATD, pd + (size_t)32 * CATD, pl + 32, 64, CATD);

    // 11) final residual
    final_k<<<dim3(HID / 256, L), 256>>>(x, pu, out);
}